// round 12
// baseline (speedup 1.0000x reference)
#include <cuda_runtime.h>
#include <cuda_bf16.h>
#include <cstdint>

#define B_ 8
#define C1_ 256
#define C2_ 512
#define H1_ 64
#define W1_ 64
#define N1_ 4096
#define H2_ 32
#define W2_ 32
#define N2_ 1024
#define CR_ 32
#define KQ_ (C1_*9)     // 2304
#define KV_ (C2_*9)     // 4608

// ---------------- scratch (device globals; no allocations) ----------------
__device__ __nv_bfloat16 g_qh[B_*CR_*N1_], g_ql[B_*CR_*N1_];  // q hi/lo [b][c][m]
__device__ __nv_bfloat16 g_kh[B_*CR_*N2_], g_kl[B_*CR_*N2_];  // k hi/lo [b][c][n]
__device__ __nv_bfloat16 g_Ph[B_*N1_*N2_];  // P hi/lo split [b][m][n]
__device__ __nv_bfloat16 g_Pl[B_*N1_*N2_];
__device__ __nv_bfloat16 g_vh[B_*C1_*N2_];  // V hi/lo split [b][c][n]
__device__ __nv_bfloat16 g_vl[B_*C1_*N2_];
__device__ __nv_bfloat16 g_i2h1[(size_t)B_*KQ_*N1_];  // im2col(x1) hi/lo
__device__ __nv_bfloat16 g_i2l1[(size_t)B_*KQ_*N1_];
__device__ __nv_bfloat16 g_i2h2[(size_t)B_*KV_*N2_];  // im2col(x2) hi/lo
__device__ __nv_bfloat16 g_i2l2[(size_t)B_*KV_*N2_];
__device__ __nv_bfloat16 g_wvh[C1_*KV_], g_wvl[C1_*KV_];
__device__ __nv_bfloat16 g_wqh[CR_*KQ_], g_wql[CR_*KQ_];
__device__ __nv_bfloat16 g_wkh[CR_*KV_], g_wkl[CR_*KV_];
__device__ float g_logit[B_*N1_];
__device__ float g_cf[B_*N1_];
__device__ float g_y[B_*C1_*9];
__device__ float g_cw[B_*C1_];

// ---------------- helpers -------------------------------------------------
__device__ __forceinline__ uint32_t smem_u32(const void* p) {
    uint32_t a;
    asm("{ .reg .u64 t; cvta.to.shared.u64 t, %1; cvt.u32.u64 %0, t; }"
        : "=r"(a) : "l"(p));
    return a;
}
__device__ __forceinline__ void ldmx4(uint32_t* r, unsigned a) {
    asm volatile("ldmatrix.sync.aligned.m8n8.x4.shared.b16 {%0,%1,%2,%3}, [%4];"
        : "=r"(r[0]), "=r"(r[1]), "=r"(r[2]), "=r"(r[3]) : "r"(a));
}
__device__ __forceinline__ void ldmx4t(uint32_t* r, unsigned a) {
    asm volatile("ldmatrix.sync.aligned.m8n8.x4.trans.shared.b16 {%0,%1,%2,%3}, [%4];"
        : "=r"(r[0]), "=r"(r[1]), "=r"(r[2]), "=r"(r[3]) : "r"(a));
}
__device__ __forceinline__ void mma16816(float* d, const uint32_t* a,
                                         const uint32_t* b) {
    asm volatile(
        "mma.sync.aligned.m16n8k16.row.col.f32.bf16.bf16.f32 "
        "{%0,%1,%2,%3}, {%4,%5,%6,%7}, {%8,%9}, {%0,%1,%2,%3};"
        : "+f"(d[0]), "+f"(d[1]), "+f"(d[2]), "+f"(d[3])
        : "r"(a[0]), "r"(a[1]), "r"(a[2]), "r"(a[3]), "r"(b[0]), "r"(b[1]));
}
__device__ __forceinline__ void bf16split2(float v0, float v1,
                                           __nv_bfloat162& h, __nv_bfloat162& l) {
    h.x = __float2bfloat16_rn(v0); h.y = __float2bfloat16_rn(v1);
    l.x = __float2bfloat16_rn(v0 - __bfloat162float(h.x));
    l.y = __float2bfloat16_rn(v1 - __bfloat162float(h.y));
}

// ---------------- fast exp on FMA pipe ------------------------------------
__device__ __forceinline__ float fexp(float x) {
    x = fmaxf(x, -80.f);
    float t = x * 1.4426950408889634f;
    float z = t + 12582912.f;
    int   i = __float_as_int(z) - 0x4B400000;
    float f = t - (z - 12582912.f);
    float y = f * 0.6931471805599453f;
    float p = 1.f/720.f;
    p = fmaf(p, y, 1.f/120.f);
    p = fmaf(p, y, 1.f/24.f);
    p = fmaf(p, y, 1.f/6.f);
    p = fmaf(p, y, 0.5f);
    p = fmaf(p, y, 1.f);
    p = fmaf(p, y, 1.f);
    return p * __int_as_float((i + 127) << 23);
}

// ---------------- weight fp32 -> bf16 hi/lo -------------------------------
__global__ __launch_bounds__(256) void wsplit_k(const float* __restrict__ w,
                                                __nv_bfloat16* __restrict__ h,
                                                __nv_bfloat16* __restrict__ l,
                                                int n)
{
    int i = blockIdx.x*256 + threadIdx.x;
    if (i >= n) return;
    float v = w[i];
    __nv_bfloat16 hv = __float2bfloat16_rn(v);
    h[i] = hv;
    l[i] = __float2bfloat16_rn(v - __bfloat162float(hv));
}

// ---------------- im2col of x2 (32x32), k = ci*9 + dy*3+dx ----------------
__global__ __launch_bounds__(256) void im2col2_k(const float* __restrict__ x2)
{
    __shared__ float img[8*1024];
    int t = threadIdx.x, cig = blockIdx.x, b = blockIdx.y;
    const float* src = x2 + ((size_t)(b*C2_ + cig*8))*N2_;
    for (int i = t; i < 8*1024; i += 256) img[i] = src[i];
    __syncthreads();
    #pragma unroll
    for (int ci = 0; ci < 8; ci++) {
        size_t kbase = (size_t)b*KV_ + (size_t)(cig*8+ci)*9;
        #pragma unroll
        for (int j = 0; j < 9; j++) {
            int dy = j/3 - 1, dx = j%3 - 1;
            size_t dst = (kbase + j)*N2_;
            #pragma unroll
            for (int rep = 0; rep < 2; rep++) {
                int n = 2*(t + 256*rep);
                int h = n >> 5, w = n & 31;
                int sh = h + dy;
                float v0 = 0.f, v1 = 0.f;
                if ((unsigned)sh < 32u) {
                    int sw0 = w + dx;
                    if ((unsigned)sw0 < 32u) v0 = img[ci*1024 + (sh<<5) + sw0];
                    if ((unsigned)(sw0+1) < 32u) v1 = img[ci*1024 + (sh<<5) + sw0 + 1];
                }
                __nv_bfloat162 hh, ll;
                bf16split2(v0, v1, hh, ll);
                *(__nv_bfloat162*)(g_i2h2 + dst + n) = hh;
                *(__nv_bfloat162*)(g_i2l2 + dst + n) = ll;
            }
        }
    }
}

// ---------------- im2col of x1 (64x64) ------------------------------------
__global__ __launch_bounds__(256) void im2col1_k(const float* __restrict__ x1)
{
    __shared__ float img[4096];
    int t = threadIdx.x, ci = blockIdx.x, b = blockIdx.y;
    const float* src = x1 + ((size_t)(b*C1_ + ci))*N1_;
    for (int i = t; i < 4096; i += 256) img[i] = src[i];
    __syncthreads();
    size_t kbase = (size_t)b*KQ_ + (size_t)ci*9;
    #pragma unroll
    for (int j = 0; j < 9; j++) {
        int dy = j/3 - 1, dx = j%3 - 1;
        size_t dst = (kbase + j)*N1_;
        #pragma unroll
        for (int rep = 0; rep < 8; rep++) {
            int n = 2*(t + 256*rep);
            int h = n >> 6, w = n & 63;
            int sh = h + dy;
            float v0 = 0.f, v1 = 0.f;
            if ((unsigned)sh < 64u) {
                int sw0 = w + dx;
                if ((unsigned)sw0 < 64u) v0 = img[(sh<<6) + sw0];
                if ((unsigned)(sw0+1) < 64u) v1 = img[(sh<<6) + sw0 + 1];
            }
            __nv_bfloat162 hh, ll;
            bf16split2(v0, v1, hh, ll);
            *(__nv_bfloat162*)(g_i2h1 + dst + n) = hh;
            *(__nv_bfloat162*)(g_i2l1 + dst + n) = ll;
        }
    }
}

// ---------------- conv_v as GEMM: D[256co][1024n] = W[co][k] I[k][n] ------
#define GV_AP 40
#define GV_BP 136
__global__ __launch_bounds__(256) void gemm_v_k()
{
    __shared__ __nv_bfloat16 Ah_s[128*GV_AP], Al_s[128*GV_AP];
    __shared__ __nv_bfloat16 Bh_s[32*GV_BP],  Bl_s[32*GV_BP];
    const int K = KV_;
    int t = threadIdx.x, b = blockIdx.z;
    int n0 = blockIdx.x*128, co0 = blockIdx.y*128;
    int lane = t & 31, wid = t >> 5;
    int wc = wid >> 2, wm = wid & 3;

    const __nv_bfloat16* Ih = g_i2h2 + (size_t)b*K*N2_;
    const __nv_bfloat16* Il = g_i2l2 + (size_t)b*K*N2_;
    int ar = t >> 2, ac = (t & 3) * 8;
    int br = t >> 4, bc = (t & 15) * 8;
    unsigned sAh = smem_u32(Ah_s), sAl = smem_u32(Al_s);
    unsigned sBh = smem_u32(Bh_s), sBl = smem_u32(Bl_s);

    float acc[4][4][4];
    #pragma unroll
    for (int i = 0; i < 4; i++)
        #pragma unroll
        for (int j = 0; j < 4; j++)
            #pragma unroll
            for (int k = 0; k < 4; k++) acc[i][j][k] = 0.f;

    for (int kb = 0; kb < K; kb += 32) {
        uint4 vah0 = *(const uint4*)(g_wvh + (size_t)(co0+ar)*K + kb + ac);
        uint4 vah1 = *(const uint4*)(g_wvh + (size_t)(co0+ar+64)*K + kb + ac);
        uint4 val0 = *(const uint4*)(g_wvl + (size_t)(co0+ar)*K + kb + ac);
        uint4 val1 = *(const uint4*)(g_wvl + (size_t)(co0+ar+64)*K + kb + ac);
        uint4 vbh0 = *(const uint4*)(Ih + (size_t)(kb+br)*N2_ + n0 + bc);
        uint4 vbh1 = *(const uint4*)(Ih + (size_t)(kb+br+16)*N2_ + n0 + bc);
        uint4 vbl0 = *(const uint4*)(Il + (size_t)(kb+br)*N2_ + n0 + bc);
        uint4 vbl1 = *(const uint4*)(Il + (size_t)(kb+br+16)*N2_ + n0 + bc);
        __syncthreads();
        *(uint4*)(Ah_s + ar*GV_AP + ac)      = vah0;
        *(uint4*)(Ah_s + (ar+64)*GV_AP + ac) = vah1;
        *(uint4*)(Al_s + ar*GV_AP + ac)      = val0;
        *(uint4*)(Al_s + (ar+64)*GV_AP + ac) = val1;
        *(uint4*)(Bh_s + br*GV_BP + bc)      = vbh0;
        *(uint4*)(Bh_s + (br+16)*GV_BP + bc) = vbh1;
        *(uint4*)(Bl_s + br*GV_BP + bc)      = vbl0;
        *(uint4*)(Bl_s + (br+16)*GV_BP + bc) = vbl1;
        __syncthreads();
        #pragma unroll
        for (int kk = 0; kk < 2; kk++) {
            uint32_t bh[2][4], bl[2][4];
            #pragma unroll
            for (int p = 0; p < 2; p++) {
                unsigned off = (unsigned)(((kk*16 + (lane&15))*GV_BP
                               + wm*32 + p*16 + 8*(lane>>4)) * 2);
                ldmx4t(bh[p], sBh + off);
                ldmx4t(bl[p], sBl + off);
            }
            #pragma unroll
            for (int ct = 0; ct < 4; ct++) {
                unsigned off = (unsigned)(((wc*64 + ct*16 + (lane&15))*GV_AP
                               + kk*16 + 8*(lane>>4)) * 2);
                uint32_t ah[4], al[4];
                ldmx4(ah, sAh + off);
                ldmx4(al, sAl + off);
                #pragma unroll
                for (int mt = 0; mt < 4; mt++) {
                    const uint32_t* pbh = bh[mt>>1] + (mt&1)*2;
                    const uint32_t* pbl = bl[mt>>1] + (mt&1)*2;
                    mma16816(acc[ct][mt], ah, pbh);
                    mma16816(acc[ct][mt], ah, pbl);
                    mma16816(acc[ct][mt], al, pbh);
                }
            }
        }
    }
    #pragma unroll
    for (int ct = 0; ct < 4; ct++) {
        int r0 = co0 + wc*64 + ct*16 + (lane>>2);
        #pragma unroll
        for (int mt = 0; mt < 4; mt++) {
            int col = n0 + wm*32 + mt*8 + 2*(lane&3);
            size_t o0 = ((size_t)(b*C1_) + r0)*N2_ + col;
            __nv_bfloat162 h, l;
            bf16split2(acc[ct][mt][0], acc[ct][mt][1], h, l);
            *(__nv_bfloat162*)(g_vh + o0) = h;
            *(__nv_bfloat162*)(g_vl + o0) = l;
            size_t o1 = o0 + (size_t)8*N2_;
            bf16split2(acc[ct][mt][2], acc[ct][mt][3], h, l);
            *(__nv_bfloat162*)(g_vh + o1) = h;
            *(__nv_bfloat162*)(g_vl + o1) = l;
        }
    }
}

// ---------------- conv_q / conv_k as GEMM: D[32co][Nn], bf16 hi/lo out ----
#define GQ_AP 40
#define GQ_BP 264
__global__ __launch_bounds__(256) void gemm_qk_k(
    const __nv_bfloat16* __restrict__ Wh, const __nv_bfloat16* __restrict__ Wl,
    const __nv_bfloat16* __restrict__ I2h, const __nv_bfloat16* __restrict__ I2l,
    __nv_bfloat16* __restrict__ oh, __nv_bfloat16* __restrict__ ol,
    int K, int Ntot)
{
    __shared__ __nv_bfloat16 Ah_s[32*GQ_AP], Al_s[32*GQ_AP];
    __shared__ __nv_bfloat16 Bh_s[32*GQ_BP], Bl_s[32*GQ_BP];
    int t = threadIdx.x, b = blockIdx.z;
    int n0 = blockIdx.x*256;
    int lane = t & 31, wm = t >> 5;
    const __nv_bfloat16* Ih = I2h + (size_t)b*K*Ntot;
    const __nv_bfloat16* Il = I2l + (size_t)b*K*Ntot;
    int ar = t >> 2, ac = (t & 3)*8;
    bool doA = (t < 128);
    unsigned sAh = smem_u32(Ah_s), sAl = smem_u32(Al_s);
    unsigned sBh = smem_u32(Bh_s), sBl = smem_u32(Bl_s);

    float acc[2][4][4];
    #pragma unroll
    for (int i = 0; i < 2; i++)
        #pragma unroll
        for (int j = 0; j < 4; j++)
            #pragma unroll
            for (int k = 0; k < 4; k++) acc[i][j][k] = 0.f;

    for (int kb = 0; kb < K; kb += 32) {
        uint4 sa_h, sa_l;
        if (doA) {
            sa_h = *(const uint4*)(Wh + (size_t)ar*K + kb + ac);
            sa_l = *(const uint4*)(Wl + (size_t)ar*K + kb + ac);
        }
        uint4 vbh[4], vbl[4];
        #pragma unroll
        for (int j = 0; j < 4; j++) {
            int i = t + 256*j;
            int r = i >> 5, c8 = (i & 31)*8;
            vbh[j] = *(const uint4*)(Ih + (size_t)(kb+r)*Ntot + n0 + c8);
            vbl[j] = *(const uint4*)(Il + (size_t)(kb+r)*Ntot + n0 + c8);
        }
        __syncthreads();
        if (doA) {
            *(uint4*)(Ah_s + ar*GQ_AP + ac) = sa_h;
            *(uint4*)(Al_s + ar*GQ_AP + ac) = sa_l;
        }
        #pragma unroll
        for (int j = 0; j < 4; j++) {
            int i = t + 256*j;
            int r = i >> 5, c8 = (i & 31)*8;
            *(uint4*)(Bh_s + r*GQ_BP + c8) = vbh[j];
            *(uint4*)(Bl_s + r*GQ_BP + c8) = vbl[j];
        }
        __syncthreads();
        #pragma unroll
        for (int kk = 0; kk < 2; kk++) {
            uint32_t bh[2][4], bl[2][4];
            #pragma unroll
            for (int p = 0; p < 2; p++) {
                unsigned off = (unsigned)(((kk*16 + (lane&15))*GQ_BP
                               + wm*32 + p*16 + 8*(lane>>4)) * 2);
                ldmx4t(bh[p], sBh + off);
                ldmx4t(bl[p], sBl + off);
            }
            #pragma unroll
            for (int ct = 0; ct < 2; ct++) {
                unsigned off = (unsigned)(((ct*16 + (lane&15))*GQ_AP
                               + kk*16 + 8*(lane>>4)) * 2);
                uint32_t ah[4], al[4];
                ldmx4(ah, sAh + off);
                ldmx4(al, sAl + off);
                #pragma unroll
                for (int mt = 0; mt < 4; mt++) {
                    const uint32_t* pbh = bh[mt>>1] + (mt&1)*2;
                    const uint32_t* pbl = bl[mt>>1] + (mt&1)*2;
                    mma16816(acc[ct][mt], ah, pbh);
                    mma16816(acc[ct][mt], ah, pbl);
                    mma16816(acc[ct][mt], al, pbh);
                }
            }
        }
    }
    #pragma unroll
    for (int ct = 0; ct < 2; ct++) {
        int r0 = ct*16 + (lane>>2);
        #pragma unroll
        for (int mt = 0; mt < 4; mt++) {
            int col = n0 + wm*32 + mt*8 + 2*(lane&3);
            size_t o0 = ((size_t)(b*CR_) + r0)*Ntot + col;
            __nv_bfloat162 h, l;
            bf16split2(acc[ct][mt][0], acc[ct][mt][1], h, l);
            *(__nv_bfloat162*)(oh + o0) = h;
            *(__nv_bfloat162*)(ol + o0) = l;
            size_t o1 = o0 + (size_t)8*Ntot;
            bf16split2(acc[ct][mt][2], acc[ct][mt][3], h, l);
            *(__nv_bfloat162*)(oh + o1) = h;
            *(__nv_bfloat162*)(ol + o1) = l;
        }
    }
}

// ---------------- fused S-GEMM + softmax: emit P bf16 hi/lo ---------------
// CTA = (b, 32 m-rows). Scores [32][SP_] fp32 in smem; K streamed in chunks.
// Q tile TRANSPOSED into [m][c] smem so the validated non-trans A recipe
// applies; B side identical to gemm_qk_k's validated trans recipe.
#define SP_ 1036
#define QP_ 40
#define KP_ 264
#define SF_SMEM (32*SP_*4 + 2*(32*QP_*2) + 2*(32*KP_*2))
__global__ __launch_bounds__(256) void s_fused_k()
{
    extern __shared__ char smraw[];
    float* S_s = (float*)smraw;
    __nv_bfloat16* Qh_s = (__nv_bfloat16*)(smraw + 32*SP_*4);  // [m][c]
    __nv_bfloat16* Ql_s = Qh_s + 32*QP_;
    __nv_bfloat16* Kh_s = Ql_s + 32*QP_;                       // [c][n]
    __nv_bfloat16* Kl_s = Kh_s + 32*KP_;
    int t = threadIdx.x, b = blockIdx.y;
    int m0 = blockIdx.x*32;
    int lane = t & 31, w = t >> 5;

    // load Q tile [32c][32m] from gmem, store TRANSPOSED as [m][c]
    {
        int tt = t & 127;
        int c = tt >> 2, m8 = (tt & 3)*8;
        const __nv_bfloat16* src = (t < 128) ? g_qh : g_ql;
        __nv_bfloat16* dst = (t < 128) ? Qh_s : Ql_s;
        uint4 v = *(const uint4*)(src + ((size_t)(b*CR_ + c))*N1_ + m0 + m8);
        __nv_bfloat16 tmp[8];
        *(uint4*)tmp = v;
        #pragma unroll
        for (int e = 0; e < 8; e++) dst[(m8+e)*QP_ + c] = tmp[e];
    }
    unsigned sQh = smem_u32(Qh_s), sQl = smem_u32(Ql_s);
    unsigned sKh = smem_u32(Kh_s), sKl = smem_u32(Kl_s);

    for (int nb = 0; nb < N2_; nb += 256) {
        uint4 vkh[4], vkl[4];
        #pragma unroll
        for (int j = 0; j < 4; j++) {
            int i = t + 256*j;
            int r = i >> 5, c8 = (i & 31)*8;
            vkh[j] = *(const uint4*)(g_kh + ((size_t)(b*CR_ + r))*N2_ + nb + c8);
            vkl[j] = *(const uint4*)(g_kl + ((size_t)(b*CR_ + r))*N2_ + nb + c8);
        }
        __syncthreads();             // prior chunk's mma readers done (covers Q too)
        #pragma unroll
        for (int j = 0; j < 4; j++) {
            int i = t + 256*j;
            int r = i >> 5, c8 = (i & 31)*8;
            *(uint4*)(Kh_s + r*KP_ + c8) = vkh[j];
            *(uint4*)(Kl_s + r*KP_ + c8) = vkl[j];
        }
        __syncthreads();
        // warp w computes 32m x 32n at n = nb + w*32
        float acc[2][4][4];
        #pragma unroll
        for (int i = 0; i < 2; i++)
            #pragma unroll
            for (int j = 0; j < 4; j++)
                #pragma unroll
                for (int k = 0; k < 4; k++) acc[i][j][k] = 0.f;
        #pragma unroll
        for (int kk = 0; kk < 2; kk++) {
            uint32_t bh[2][4], bl[2][4];
            #pragma unroll
            for (int p = 0; p < 2; p++) {
                unsigned off = (unsigned)(((kk*16 + (lane&15))*KP_
                               + w*32 + p*16 + 8*(lane>>4)) * 2);
                ldmx4t(bh[p], sKh + off);
                ldmx4t(bl[p], sKl + off);
            }
            #pragma unroll
            for (int ct = 0; ct < 2; ct++) {
                // validated non-trans A recipe from [m][k] storage
                unsigned off = (unsigned)(((ct*16 + (lane&15))*QP_
                               + kk*16 + 8*(lane>>4)) * 2);
                uint32_t ah[4], al[4];
                ldmx4(ah, sQh + off);
                ldmx4(al, sQl + off);
                #pragma unroll
                for (int mt = 0; mt < 4; mt++) {
                    const uint32_t* pbh = bh[mt>>1] + (mt&1)*2;
                    const uint32_t* pbl = bl[mt>>1] + (mt&1)*2;
                    mma16816(acc[ct][mt], ah, pbh);
                    mma16816(acc[ct][mt], ah, pbl);
                    mma16816(acc[ct][mt], al, pbh);
                }
            }
        }
        // write scores to smem
        #pragma unroll
        for (int ct = 0; ct < 2; ct++) {
            int m = ct*16 + (lane>>2);
            #pragma unroll
            for (int mt = 0; mt < 4; mt++) {
                int col = nb + w*32 + mt*8 + 2*(lane&3);
                *(float2*)(S_s + m*SP_ + col) =
                    make_float2(acc[ct][mt][0], acc[ct][mt][1]);
                *(float2*)(S_s + (m+8)*SP_ + col) =
                    make_float2(acc[ct][mt][2], acc[ct][mt][3]);
            }
        }
    }
    __syncthreads();

    // per-row softmax over n (8 threads per row)
    {
        int m = t >> 3, g = t & 7;
        float* row = S_s + m*SP_;
        float mx = -3e38f;
        for (int i = g; i < 256; i += 8) {
            float4 v = *(float4*)(row + 4*i);
            mx = fmaxf(mx, fmaxf(fmaxf(v.x, v.y), fmaxf(v.z, v.w)));
        }
        #pragma unroll
        for (int o = 4; o; o >>= 1) mx = fmaxf(mx, __shfl_xor_sync(~0u, mx, o));
        float s = 0.f;
        for (int i = g; i < 256; i += 8) {
            float4 v = *(float4*)(row + 4*i);
            v.x = fexp(v.x - mx); v.y = fexp(v.y - mx);
            v.z = fexp(v.z - mx); v.w = fexp(v.w - mx);
            s += v.x + v.y + v.z + v.w;
            *(float4*)(row + 4*i) = v;
        }
        #pragma unroll
        for (int o = 4; o; o >>= 1) s += __shfl_xor_sync(~0u, s, o);
        float inv = 1.f / s;
        size_t base = ((size_t)(b*N1_) + m0 + m)*N2_;
        for (int i = g; i < 256; i += 8) {
            float4 v = *(float4*)(row + 4*i);
            __nv_bfloat162 h0, h1, l0, l1;
            bf16split2(v.x*inv, v.y*inv, h0, l0);
            bf16split2(v.z*inv, v.w*inv, h1, l1);
            *(__nv_bfloat162*)(g_Ph + base + 4*i)     = h0;
            *(__nv_bfloat162*)(g_Ph + base + 4*i + 2) = h1;
            *(__nv_bfloat162*)(g_Pl + base + 4*i)     = l0;
            *(__nv_bfloat162*)(g_Pl + base + 4*i + 2) = l1;
        }
    }
}

// ---------------- mma.sync O-GEMM: O[c][m] = sum_n V[c][n] P[m][n] --------
#define OSTR 40
__global__ __launch_bounds__(256) void o_mma_k(const float* __restrict__ x1,
                                               float* __restrict__ out)
{
    __shared__ __nv_bfloat16 Ah_s[128*OSTR], Al_s[128*OSTR];
    __shared__ __nv_bfloat16 Bh_s[128*OSTR], Bl_s[128*OSTR];
    int t = threadIdx.x, b = blockIdx.z;
    int m0 = blockIdx.x*128, c0 = blockIdx.y*128;
    int lane = t & 31, wid = t >> 5;
    int wc = wid >> 2, wm = wid & 3;
    int r = t >> 1, half = t & 1;

    const __nv_bfloat16* srcAh = g_vh + ((size_t)(b*C1_ + c0 + r))*N2_ + half*16;
    const __nv_bfloat16* srcAl = g_vl + ((size_t)(b*C1_ + c0 + r))*N2_ + half*16;
    const __nv_bfloat16* srcBh = g_Ph + ((size_t)(b*N1_ + m0 + r))*N2_ + half*16;
    const __nv_bfloat16* srcBl = g_Pl + ((size_t)(b*N1_ + m0 + r))*N2_ + half*16;
    unsigned dA_h = smem_u32(Ah_s) + (unsigned)((r*OSTR + half*16) * 2);
    unsigned dA_l = smem_u32(Al_s) + (unsigned)((r*OSTR + half*16) * 2);
    unsigned dB_h = smem_u32(Bh_s) + (unsigned)((r*OSTR + half*16) * 2);
    unsigned dB_l = smem_u32(Bl_s) + (unsigned)((r*OSTR + half*16) * 2);

    unsigned aAh = smem_u32(Ah_s), aAl = smem_u32(Al_s);
    unsigned aBh = smem_u32(Bh_s), aBl = smem_u32(Bl_s);
    int arow = wc*64 + (lane & 15);
    int acol = (lane >> 4) * 8;
    int brow = wm*32 + (lane & 7) + ((lane >> 4) << 3);
    int bcol = ((lane >> 3) & 1) * 8;

    float acc[4][4][4];
    #pragma unroll
    for (int i = 0; i < 4; i++)
        #pragma unroll
        for (int j = 0; j < 4; j++)
            #pragma unroll
            for (int k = 0; k < 4; k++) acc[i][j][k] = 0.f;

    for (int nb = 0; nb < N2_; nb += 32) {
        uint4 vah0 = *(const uint4*)(srcAh + nb);
        uint4 vah1 = *(const uint4*)(srcAh + nb + 8);
        uint4 val0 = *(const uint4*)(srcAl + nb);
        uint4 val1 = *(const uint4*)(srcAl + nb + 8);
        uint4 vbh0 = *(const uint4*)(srcBh + nb);
        uint4 vbh1 = *(const uint4*)(srcBh + nb + 8);
        uint4 vbl0 = *(const uint4*)(srcBl + nb);
        uint4 vbl1 = *(const uint4*)(srcBl + nb + 8);
        __syncthreads();
        *(uint4*)(__cvta_shared_to_generic(dA_h))      = vah0;
        *(uint4*)(__cvta_shared_to_generic(dA_h + 16)) = vah1;
        *(uint4*)(__cvta_shared_to_generic(dA_l))      = val0;
        *(uint4*)(__cvta_shared_to_generic(dA_l + 16)) = val1;
        *(uint4*)(__cvta_shared_to_generic(dB_h))      = vbh0;
        *(uint4*)(__cvta_shared_to_generic(dB_h + 16)) = vbh1;
        *(uint4*)(__cvta_shared_to_generic(dB_l))      = vbl0;
        *(uint4*)(__cvta_shared_to_generic(dB_l + 16)) = vbl1;
        __syncthreads();
        #pragma unroll
        for (int kk = 0; kk < 2; kk++) {
            int kc = kk*16;
            uint32_t bh[8], bl[8];
            #pragma unroll
            for (int pair = 0; pair < 2; pair++) {
                unsigned off = (unsigned)(((brow + pair*16)*OSTR + bcol + kc) * 2);
                ldmx4(bh + pair*4, aBh + off);
                ldmx4(bl + pair*4, aBl + off);
            }
            #pragma unroll
            for (int ct = 0; ct < 4; ct++) {
                unsigned off = (unsigned)(((arow + ct*16)*OSTR + acol + kc) * 2);
                uint32_t ah[4], al[4];
                ldmx4(ah, aAh + off);
                ldmx4(al, aAl + off);
                #pragma unroll
                for (int mt = 0; mt < 4; mt++) {
                    const uint32_t* pbh = bh + (mt >> 1)*4 + (mt & 1)*2;
                    const uint32_t* pbl = bl + (mt >> 1)*4 + (mt & 1)*2;
                    mma16816(acc[ct][mt], ah, pbh);
                    mma16816(acc[ct][mt], ah, pbl);
                    mma16816(acc[ct][mt], al, pbh);
                }
            }
        }
    }

    int colb = 2*(lane & 3);
    #pragma unroll
    for (int ct = 0; ct < 4; ct++) {
        int cb = c0 + wc*64 + ct*16 + (lane >> 2);
        float cw0 = 1.f + g_cw[b*C1_ + cb];
        float cw1 = 1.f + g_cw[b*C1_ + cb + 8];
        #pragma unroll
        for (int mt = 0; mt < 4; mt++) {
            int m = m0 + wm*32 + mt*8 + colb;
            size_t o0 = ((size_t)(b*C1_ + cb))*N1_ + m;
            size_t o1 = ((size_t)(b*C1_ + cb + 8))*N1_ + m;
            float2 x0 = *(const float2*)(x1 + o0);
            float2 x1v = *(const float2*)(x1 + o1);
            *(float2*)(out + o0) = make_float2(fmaf(x0.x, cw0, acc[ct][mt][0]),
                                               fmaf(x0.y, cw0, acc[ct][mt][1]));
            *(float2*)(out + o1) = make_float2(fmaf(x1v.x, cw1, acc[ct][mt][2]),
                                               fmaf(x1v.y, cw1, acc[ct][mt][3]));
        }
    }
}

// ---------------- channel branch: cf logits (1x1 conv) --------------------
__global__ __launch_bounds__(256) void cf_logit_k(const float* __restrict__ x1,
                                                  const float* __restrict__ wc)
{
    __shared__ float wc_s[C1_];
    int t = threadIdx.x, b = blockIdx.y;
    wc_s[t] = wc[t];
    __syncthreads();
    int n = blockIdx.x*256 + t;
    const float* xp = x1 + (size_t)b*C1_*N1_ + n;
    float s0 = 0.f, s1 = 0.f, s2 = 0.f, s3 = 0.f;
    #pragma unroll 4
    for (int c = 0; c < C1_; c += 4) {
        s0 = fmaf(wc_s[c+0], __ldg(xp + (size_t)(c+0)*N1_), s0);
        s1 = fmaf(wc_s[c+1], __ldg(xp + (size_t)(c+1)*N1_), s1);
        s2 = fmaf(wc_s[c+2], __ldg(xp + (size_t)(c+2)*N1_), s2);
        s3 = fmaf(wc_s[c+3], __ldg(xp + (size_t)(c+3)*N1_), s3);
    }
    g_logit[b*N1_ + n] = (s0 + s1) + (s2 + s3);
}

// ---------------- cf softmax over N1 (per b) -------------------------------
__global__ __launch_bounds__(1024) void cf_softmax_k()
{
    int b = blockIdx.x, t = threadIdx.x;
    __shared__ float red[32];
    float v[4];
    #pragma unroll
    for (int i = 0; i < 4; i++) v[i] = g_logit[b*N1_ + t + 1024*i];
    float mx = fmaxf(fmaxf(v[0],v[1]), fmaxf(v[2],v[3]));
    #pragma unroll
    for (int o = 16; o; o >>= 1) mx = fmaxf(mx, __shfl_xor_sync(~0u, mx, o));
    if ((t&31) == 0) red[t>>5] = mx;
    __syncthreads();
    if (t < 32) {
        float m2 = red[t];
        #pragma unroll
        for (int o = 16; o; o >>= 1) m2 = fmaxf(m2, __shfl_xor_sync(~0u, m2, o));
        red[t] = m2;
    }
    __syncthreads();
    mx = red[0];
    __syncthreads();
    float e[4]; float s = 0.f;
    #pragma unroll
    for (int i = 0; i < 4; i++) { e[i] = fexp(v[i]-mx); s += e[i]; }
    #pragma unroll
    for (int o = 16; o; o >>= 1) s += __shfl_xor_sync(~0u, s, o);
    if ((t&31) == 0) red[t>>5] = s;
    __syncthreads();
    if (t < 32) {
        float s2 = red[t];
        #pragma unroll
        for (int o = 16; o; o >>= 1) s2 += __shfl_xor_sync(~0u, s2, o);
        red[t] = s2;
    }
    __syncthreads();
    float inv = 1.f / red[0];
    #pragma unroll
    for (int i = 0; i < 4; i++) g_cf[b*N1_ + t + 1024*i] = e[i]*inv;
}

// ---------------- y[b,i,dy,dx] = sum_p x1[b,i,p]*cf_pad[b, p-(dy-1,dx-1)] --
__global__ __launch_bounds__(256) void y_k(const float* __restrict__ x1)
{
    __shared__ float cf_s[N1_];
    __shared__ float part[8][9];
    int i = blockIdx.x, b = blockIdx.y, t = threadIdx.x;
    for (int idx = t; idx < N1_; idx += 256) cf_s[idx] = g_cf[b*N1_ + idx];
    __syncthreads();
    float a[9];
    #pragma unroll
    for (int k = 0; k < 9; k++) a[k] = 0.f;
    const float* xp = x1 + ((size_t)(b*C1_ + i))*N1_;
    for (int p = t; p < N1_; p += 256) {
        float xv = xp[p];
        int ph = p >> 6, pw = p & 63;
        #pragma unroll
        for (int dy = 0; dy < 3; dy++) {
            int qh = ph + 1 - dy;
            if ((unsigned)qh < 64u) {
                #pragma unroll
                for (int dx = 0; dx < 3; dx++) {
                    int qw = pw + 1 - dx;
                    if ((unsigned)qw < 64u)
                        a[dy*3+dx] = fmaf(xv, cf_s[(qh<<6)+qw], a[dy*3+dx]);
                }
            }
        }
    }
    #pragma unroll
    for (int k = 0; k < 9; k++) {
        float s = a[k];
        #pragma unroll
        for (int o = 16; o; o >>= 1) s += __shfl_xor_sync(~0u, s, o);
        if ((t&31) == 0) part[t>>5][k] = s;
    }
    __syncthreads();
    if (t < 9) {
        float s = 0.f;
        #pragma unroll
        for (int w = 0; w < 8; w++) s += part[w][t];
        g_y[(b*C1_+i)*9 + t] = s;
    }
}

// ---------------- pool = wch*y ; t = wt1*pool ; LN ; relu ; cw = wt2*t -----
__global__ __launch_bounds__(256) void chtail_k(
    const float* __restrict__ wch, const float* __restrict__ wt1,
    const float* __restrict__ bt1, const float* __restrict__ lng,
    const float* __restrict__ lnb, const float* __restrict__ wt2,
    const float* __restrict__ bt2)
{
    __shared__ float y_s[C1_*9];
    __shared__ float pool_s[C1_];
    __shared__ float t_s[CR_];
    int b = blockIdx.x, t = threadIdx.x;
    for (int idx = t; idx < C1_*9; idx += 256) y_s[idx] = g_y[b*C1_*9 + idx];
    __syncthreads();
    {
        float a = 0.f;
        const float* wp = wch + (size_t)t*(C1_*9);
        #pragma unroll 4
        for (int idx = 0; idx < C1_*9; idx++) a = fmaf(wp[idx], y_s[idx], a);
        pool_s[t] = a;
    }
    __syncthreads();
    if (t < CR_) {
        float tv = bt1[t];
        const float* wp = wt1 + t*C1_;
        #pragma unroll 4
        for (int c = 0; c < C1_; c++) tv = fmaf(wp[c], pool_s[c], tv);
        float s1 = tv;
        #pragma unroll
        for (int o = 16; o; o >>= 1) s1 += __shfl_xor_sync(~0u, s1, o);
        float mu = s1 * (1.f/32.f);
        float d  = tv - mu;
        float s2 = d*d;
        #pragma unroll
        for (int o = 16; o; o >>= 1) s2 += __shfl_xor_sync(~0u, s2, o);
        float var = s2 * (1.f/32.f);
        float val = d * rsqrtf(var + 1e-5f) * lng[t] + lnb[t];
        t_s[t] = fmaxf(val, 0.f);
    }
    __syncthreads();
    {
        float a = bt2[t];
        const float* wp = wt2 + t*CR_;
        #pragma unroll
        for (int j = 0; j < CR_; j++) a = fmaf(wp[j], t_s[j], a);
        g_cw[b*C1_ + t] = a;
    }
}

// ---------------------------------------------------------------------------
extern "C" void kernel_launch(void* const* d_in, const int* in_sizes, int n_in,
                              void* d_out, int out_size)
{
    (void)in_sizes; (void)n_in; (void)out_size;
    const float* x1  = (const float*)d_in[0];
    const float* x2  = (const float*)d_in[1];
    const float* wq  = (const float*)d_in[2];
    const float* wk  = (const float*)d_in[3];
    const float* wv  = (const float*)d_in[4];
    const float* wc  = (const float*)d_in[5];
    const float* wch = (const float*)d_in[6];
    const float* wt1 = (const float*)d_in[7];
    const float* bt1 = (const float*)d_in[8];
    const float* lng = (const float*)d_in[9];
    const float* lnb = (const float*)d_in[10];
    const float* wt2 = (const float*)d_in[11];
    const float* bt2 = (const float*)d_in[12];
    float* out = (float*)d_out;

    __nv_bfloat16 *pwvh, *pwvl, *pwqh, *pwql, *pwkh, *pwkl;
    __nv_bfloat16 *pi2h1, *pi2l1, *pi2h2, *pi2l2;
    __nv_bfloat16 *pqh, *pql, *pkh, *pkl;
    cudaGetSymbolAddress((void**)&pwvh,  g_wvh);
    cudaGetSymbolAddress((void**)&pwvl,  g_wvl);
    cudaGetSymbolAddress((void**)&pwqh,  g_wqh);
    cudaGetSymbolAddress((void**)&pwql,  g_wql);
    cudaGetSymbolAddress((void**)&pwkh,  g_wkh);
    cudaGetSymbolAddress((void**)&pwkl,  g_wkl);
    cudaGetSymbolAddress((void**)&pi2h1, g_i2h1);
    cudaGetSymbolAddress((void**)&pi2l1, g_i2l1);
    cudaGetSymbolAddress((void**)&pi2h2, g_i2h2);
    cudaGetSymbolAddress((void**)&pi2l2, g_i2l2);
    cudaGetSymbolAddress((void**)&pqh,   g_qh);
    cudaGetSymbolAddress((void**)&pql,   g_ql);
    cudaGetSymbolAddress((void**)&pkh,   g_kh);
    cudaGetSymbolAddress((void**)&pkl,   g_kl);

    // im2col + weight splits
    im2col2_k<<<dim3(C2_/8, B_), 256>>>(x2);
    im2col1_k<<<dim3(C1_, B_), 256>>>(x1);
    wsplit_k<<<(C1_*KV_ + 255)/256, 256>>>(wv, pwvh, pwvl, C1_*KV_);
    wsplit_k<<<(CR_*KQ_ + 255)/256, 256>>>(wq, pwqh, pwql, CR_*KQ_);
    wsplit_k<<<(CR_*KV_ + 255)/256, 256>>>(wk, pwkh, pwkl, CR_*KV_);

    // convs as tensor-core GEMMs (q/k emit bf16 hi/lo directly)
    gemm_v_k<<<dim3(N2_/128, C1_/128, B_), 256>>>();
    gemm_qk_k<<<dim3(N1_/256, 1, B_), 256>>>(pwqh, pwql, pi2h1, pi2l1,
                                             pqh, pql, KQ_, N1_);
    gemm_qk_k<<<dim3(N2_/256, 1, B_), 256>>>(pwkh, pwkl, pi2h2, pi2l2,
                                             pkh, pkl, KV_, N2_);

    // channel branch
    cf_logit_k<<<dim3(N1_/256, B_), 256>>>(x1, wc);
    cf_softmax_k<<<B_, 1024>>>();
    y_k<<<dim3(C1_, B_), 256>>>(x1);
    chtail_k<<<B_, 256>>>(wch, wt1, bt1, lng, lnb, wt2, bt2);

    // fused S-GEMM + softmax (mma.sync, scores in smem) -> o_mma
    cudaFuncSetAttribute(s_fused_k, cudaFuncAttributeMaxDynamicSharedMemorySize,
                         SF_SMEM);
    s_fused_k<<<dim3(N1_/32, B_), 256, SF_SMEM>>>();
    o_mma_k<<<dim3(N1_/128, C1_/128, B_), 256>>>(x1, out);
}

// round 14
// speedup vs baseline: 1.3498x; 1.3498x over previous
#include <cuda_runtime.h>
#include <cuda_bf16.h>
#include <cstdint>

#define B_ 8
#define C1_ 256
#define C2_ 512
#define H1_ 64
#define W1_ 64
#define N1_ 4096
#define H2_ 32
#define W2_ 32
#define N2_ 1024
#define CR_ 32
#define KQ_ (C1_*9)     // 2304
#define KV_ (C2_*9)     // 4608

// ---------------- scratch (device globals; no allocations) ----------------
__device__ __nv_bfloat16 g_qh[B_*CR_*N1_], g_ql[B_*CR_*N1_];  // q hi/lo [b][c][m]
__device__ __nv_bfloat16 g_kh[B_*CR_*N2_], g_kl[B_*CR_*N2_];  // k hi/lo [b][c][n]
__device__ __nv_bfloat16 g_Ph[B_*N1_*N2_];  // P (bf16, normalized) [b][m][n]
__device__ __nv_bfloat16 g_vh[B_*C1_*N2_];  // V hi/lo split [b][c][n]
__device__ __nv_bfloat16 g_vl[B_*C1_*N2_];
__device__ __nv_bfloat16 g_i2h1[(size_t)B_*KQ_*N1_];  // im2col(x1) hi/lo
__device__ __nv_bfloat16 g_i2l1[(size_t)B_*KQ_*N1_];
__device__ __nv_bfloat16 g_i2h2[(size_t)B_*KV_*N2_];  // im2col(x2) hi/lo
__device__ __nv_bfloat16 g_i2l2[(size_t)B_*KV_*N2_];
__device__ __nv_bfloat16 g_wvh[C1_*KV_], g_wvl[C1_*KV_];
__device__ __nv_bfloat16 g_wqh[CR_*KQ_], g_wql[CR_*KQ_];
__device__ __nv_bfloat16 g_wkh[CR_*KV_], g_wkl[CR_*KV_];
__device__ float g_logit[B_*N1_];
__device__ float g_cf[B_*N1_];
__device__ float g_y[B_*C1_*9];
__device__ float g_cw[B_*C1_];

// ---------------- helpers -------------------------------------------------
__device__ __forceinline__ uint32_t smem_u32(const void* p) {
    uint32_t a;
    asm("{ .reg .u64 t; cvta.to.shared.u64 t, %1; cvt.u32.u64 %0, t; }"
        : "=r"(a) : "l"(p));
    return a;
}
__device__ __forceinline__ void ldmx4(uint32_t* r, unsigned a) {
    asm volatile("ldmatrix.sync.aligned.m8n8.x4.shared.b16 {%0,%1,%2,%3}, [%4];"
        : "=r"(r[0]), "=r"(r[1]), "=r"(r[2]), "=r"(r[3]) : "r"(a));
}
__device__ __forceinline__ void ldmx4t(uint32_t* r, unsigned a) {
    asm volatile("ldmatrix.sync.aligned.m8n8.x4.trans.shared.b16 {%0,%1,%2,%3}, [%4];"
        : "=r"(r[0]), "=r"(r[1]), "=r"(r[2]), "=r"(r[3]) : "r"(a));
}
__device__ __forceinline__ void mma16816(float* d, const uint32_t* a,
                                         const uint32_t* b) {
    asm volatile(
        "mma.sync.aligned.m16n8k16.row.col.f32.bf16.bf16.f32 "
        "{%0,%1,%2,%3}, {%4,%5,%6,%7}, {%8,%9}, {%0,%1,%2,%3};"
        : "+f"(d[0]), "+f"(d[1]), "+f"(d[2]), "+f"(d[3])
        : "r"(a[0]), "r"(a[1]), "r"(a[2]), "r"(a[3]), "r"(b[0]), "r"(b[1]));
}
__device__ __forceinline__ void bf16split2(float v0, float v1,
                                           __nv_bfloat162& h, __nv_bfloat162& l) {
    h.x = __float2bfloat16_rn(v0); h.y = __float2bfloat16_rn(v1);
    l.x = __float2bfloat16_rn(v0 - __bfloat162float(h.x));
    l.y = __float2bfloat16_rn(v1 - __bfloat162float(h.y));
}

// ---------------- fast exp on FMA pipe ------------------------------------
__device__ __forceinline__ float fexp(float x) {
    x = fmaxf(x, -80.f);
    float t = x * 1.4426950408889634f;
    float z = t + 12582912.f;
    int   i = __float_as_int(z) - 0x4B400000;
    float f = t - (z - 12582912.f);
    float y = f * 0.6931471805599453f;
    float p = 1.f/720.f;
    p = fmaf(p, y, 1.f/120.f);
    p = fmaf(p, y, 1.f/24.f);
    p = fmaf(p, y, 1.f/6.f);
    p = fmaf(p, y, 0.5f);
    p = fmaf(p, y, 1.f);
    p = fmaf(p, y, 1.f);
    return p * __int_as_float((i + 127) << 23);
}

// ============================================================================
// prep_k: im2col2 | im2col1 | wsplit x3 | cf_logit  (block-role dispatch)
// ============================================================================
__device__ __forceinline__ void wsplit_body(const float* __restrict__ w,
                                            __nv_bfloat16* __restrict__ h,
                                            __nv_bfloat16* __restrict__ l,
                                            int i, int n)
{
    if (i >= n) return;
    float v = w[i];
    __nv_bfloat16 hv = __float2bfloat16_rn(v);
    h[i] = hv;
    l[i] = __float2bfloat16_rn(v - __bfloat162float(hv));
}

__global__ __launch_bounds__(256) void prep_k(
    const float* __restrict__ x1, const float* __restrict__ x2,
    const float* __restrict__ wq, const float* __restrict__ wk,
    const float* __restrict__ wv, const float* __restrict__ wc)
{
    __shared__ float sh[8*1024];
    int bx = blockIdx.x, t = threadIdx.x;

    if (bx < 512) {                       // ---- im2col2 (x2 32x32) ----
        int cig = bx & 63, b = bx >> 6;
        const float* src = x2 + ((size_t)(b*C2_ + cig*8))*N2_;
        for (int i = t; i < 8*1024; i += 256) sh[i] = src[i];
        __syncthreads();
        #pragma unroll
        for (int ci = 0; ci < 8; ci++) {
            size_t kbase = (size_t)b*KV_ + (size_t)(cig*8+ci)*9;
            #pragma unroll
            for (int j = 0; j < 9; j++) {
                int dy = j/3 - 1, dx = j%3 - 1;
                size_t dst = (kbase + j)*N2_;
                #pragma unroll
                for (int rep = 0; rep < 2; rep++) {
                    int n = 2*(t + 256*rep);
                    int h = n >> 5, w = n & 31;
                    int shh = h + dy;
                    float v0 = 0.f, v1 = 0.f;
                    if ((unsigned)shh < 32u) {
                        int sw0 = w + dx;
                        if ((unsigned)sw0 < 32u) v0 = sh[ci*1024 + (shh<<5) + sw0];
                        if ((unsigned)(sw0+1) < 32u) v1 = sh[ci*1024 + (shh<<5) + sw0 + 1];
                    }
                    __nv_bfloat162 hh, ll;
                    bf16split2(v0, v1, hh, ll);
                    *(__nv_bfloat162*)(g_i2h2 + dst + n) = hh;
                    *(__nv_bfloat162*)(g_i2l2 + dst + n) = ll;
                }
            }
        }
    } else if (bx < 2560) {               // ---- im2col1 (x1 64x64) ----
        int j0 = bx - 512;
        int ci = j0 & 255, b = j0 >> 8;
        const float* src = x1 + ((size_t)(b*C1_ + ci))*N1_;
        for (int i = t; i < 4096; i += 256) sh[i] = src[i];
        __syncthreads();
        size_t kbase = (size_t)b*KQ_ + (size_t)ci*9;
        #pragma unroll
        for (int j = 0; j < 9; j++) {
            int dy = j/3 - 1, dx = j%3 - 1;
            size_t dst = (kbase + j)*N1_;
            #pragma unroll
            for (int rep = 0; rep < 8; rep++) {
                int n = 2*(t + 256*rep);
                int h = n >> 6, w = n & 63;
                int shh = h + dy;
                float v0 = 0.f, v1 = 0.f;
                if ((unsigned)shh < 64u) {
                    int sw0 = w + dx;
                    if ((unsigned)sw0 < 64u) v0 = sh[(shh<<6) + sw0];
                    if ((unsigned)(sw0+1) < 64u) v1 = sh[(shh<<6) + sw0 + 1];
                }
                __nv_bfloat162 hh, ll;
                bf16split2(v0, v1, hh, ll);
                *(__nv_bfloat162*)(g_i2h1 + dst + n) = hh;
                *(__nv_bfloat162*)(g_i2l1 + dst + n) = ll;
            }
        }
    } else if (bx < 7168) {               // ---- wsplit wv ----
        wsplit_body(wv, g_wvh, g_wvl, (bx-2560)*256 + t, C1_*KV_);
    } else if (bx < 7456) {               // ---- wsplit wq ----
        wsplit_body(wq, g_wqh, g_wql, (bx-7168)*256 + t, CR_*KQ_);
    } else if (bx < 8032) {               // ---- wsplit wk ----
        wsplit_body(wk, g_wkh, g_wkl, (bx-7456)*256 + t, CR_*KV_);
    } else {                              // ---- cf_logit ----
        int j0 = bx - 8032;
        int nblk = j0 & 15, b = j0 >> 4;
        float* wc_s = sh;
        wc_s[t] = wc[t];
        __syncthreads();
        int n = nblk*256 + t;
        const float* xp = x1 + (size_t)b*C1_*N1_ + n;
        float s0 = 0.f, s1 = 0.f, s2 = 0.f, s3 = 0.f;
        #pragma unroll 4
        for (int c = 0; c < C1_; c += 4) {
            s0 = fmaf(wc_s[c+0], __ldg(xp + (size_t)(c+0)*N1_), s0);
            s1 = fmaf(wc_s[c+1], __ldg(xp + (size_t)(c+1)*N1_), s1);
            s2 = fmaf(wc_s[c+2], __ldg(xp + (size_t)(c+2)*N1_), s2);
            s3 = fmaf(wc_s[c+3], __ldg(xp + (size_t)(c+3)*N1_), s3);
        }
        g_logit[b*N1_ + n] = (s0 + s1) + (s2 + s3);
    }
}

// ============================================================================
// gemms_k: gemm_v | gemm_q | gemm_k | cf_softmax  (block-role dispatch)
// ============================================================================
#define GV_AP 40
#define GV_BP 136
__device__ __forceinline__ void gemm_v_body(char* shraw, int n0, int co0, int b)
{
    __nv_bfloat16* Ah_s = (__nv_bfloat16*)shraw;               // 10240 B
    __nv_bfloat16* Al_s = (__nv_bfloat16*)(shraw + 10240);     // 10240 B
    __nv_bfloat16* Bh_s = (__nv_bfloat16*)(shraw + 20480);     // 8704 B
    __nv_bfloat16* Bl_s = (__nv_bfloat16*)(shraw + 29184);     // 8704 B
    const int K = KV_;
    int t = threadIdx.x;
    int lane = t & 31, wid = t >> 5;
    int wc = wid >> 2, wm = wid & 3;

    const __nv_bfloat16* Ih = g_i2h2 + (size_t)b*K*N2_;
    const __nv_bfloat16* Il = g_i2l2 + (size_t)b*K*N2_;
    int ar = t >> 2, ac = (t & 3) * 8;
    int br = t >> 4, bc = (t & 15) * 8;
    unsigned sAh = smem_u32(Ah_s), sAl = smem_u32(Al_s);
    unsigned sBh = smem_u32(Bh_s), sBl = smem_u32(Bl_s);

    float acc[4][4][4];
    #pragma unroll
    for (int i = 0; i < 4; i++)
        #pragma unroll
        for (int j = 0; j < 4; j++)
            #pragma unroll
            for (int k = 0; k < 4; k++) acc[i][j][k] = 0.f;

    for (int kb = 0; kb < K; kb += 32) {
        uint4 vah0 = *(const uint4*)(g_wvh + (size_t)(co0+ar)*K + kb + ac);
        uint4 vah1 = *(const uint4*)(g_wvh + (size_t)(co0+ar+64)*K + kb + ac);
        uint4 val0 = *(const uint4*)(g_wvl + (size_t)(co0+ar)*K + kb + ac);
        uint4 val1 = *(const uint4*)(g_wvl + (size_t)(co0+ar+64)*K + kb + ac);
        uint4 vbh0 = *(const uint4*)(Ih + (size_t)(kb+br)*N2_ + n0 + bc);
        uint4 vbh1 = *(const uint4*)(Ih + (size_t)(kb+br+16)*N2_ + n0 + bc);
        uint4 vbl0 = *(const uint4*)(Il + (size_t)(kb+br)*N2_ + n0 + bc);
        uint4 vbl1 = *(const uint4*)(Il + (size_t)(kb+br+16)*N2_ + n0 + bc);
        __syncthreads();
        *(uint4*)(Ah_s + ar*GV_AP + ac)      = vah0;
        *(uint4*)(Ah_s + (ar+64)*GV_AP + ac) = vah1;
        *(uint4*)(Al_s + ar*GV_AP + ac)      = val0;
        *(uint4*)(Al_s + (ar+64)*GV_AP + ac) = val1;
        *(uint4*)(Bh_s + br*GV_BP + bc)      = vbh0;
        *(uint4*)(Bh_s + (br+16)*GV_BP + bc) = vbh1;
        *(uint4*)(Bl_s + br*GV_BP + bc)      = vbl0;
        *(uint4*)(Bl_s + (br+16)*GV_BP + bc) = vbl1;
        __syncthreads();
        #pragma unroll
        for (int kk = 0; kk < 2; kk++) {
            uint32_t bh[2][4], bl[2][4];
            #pragma unroll
            for (int p = 0; p < 2; p++) {
                unsigned off = (unsigned)(((kk*16 + (lane&15))*GV_BP
                               + wm*32 + p*16 + 8*(lane>>4)) * 2);
                ldmx4t(bh[p], sBh + off);
                ldmx4t(bl[p], sBl + off);
            }
            #pragma unroll
            for (int ct = 0; ct < 4; ct++) {
                unsigned off = (unsigned)(((wc*64 + ct*16 + (lane&15))*GV_AP
                               + kk*16 + 8*(lane>>4)) * 2);
                uint32_t ah[4], al[4];
                ldmx4(ah, sAh + off);
                ldmx4(al, sAl + off);
                #pragma unroll
                for (int mt = 0; mt < 4; mt++) {
                    const uint32_t* pbh = bh[mt>>1] + (mt&1)*2;
                    const uint32_t* pbl = bl[mt>>1] + (mt&1)*2;
                    mma16816(acc[ct][mt], ah, pbh);
                    mma16816(acc[ct][mt], ah, pbl);
                    mma16816(acc[ct][mt], al, pbh);
                }
            }
        }
    }
    #pragma unroll
    for (int ct = 0; ct < 4; ct++) {
        int r0 = co0 + wc*64 + ct*16 + (lane>>2);
        #pragma unroll
        for (int mt = 0; mt < 4; mt++) {
            int col = n0 + wm*32 + mt*8 + 2*(lane&3);
            size_t o0 = ((size_t)(b*C1_) + r0)*N2_ + col;
            __nv_bfloat162 h, l;
            bf16split2(acc[ct][mt][0], acc[ct][mt][1], h, l);
            *(__nv_bfloat162*)(g_vh + o0) = h;
            *(__nv_bfloat162*)(g_vl + o0) = l;
            size_t o1 = o0 + (size_t)8*N2_;
            bf16split2(acc[ct][mt][2], acc[ct][mt][3], h, l);
            *(__nv_bfloat162*)(g_vh + o1) = h;
            *(__nv_bfloat162*)(g_vl + o1) = l;
        }
    }
}

#define GQ_AP 40
#define GQ_BP 264
__device__ __forceinline__ void gemm_qk_body(char* shraw,
    const __nv_bfloat16* __restrict__ Wh, const __nv_bfloat16* __restrict__ Wl,
    const __nv_bfloat16* __restrict__ I2h, const __nv_bfloat16* __restrict__ I2l,
    __nv_bfloat16* __restrict__ oh, __nv_bfloat16* __restrict__ ol,
    int K, int Ntot, int n0, int b)
{
    __nv_bfloat16* Ah_s = (__nv_bfloat16*)shraw;               // 2560 B
    __nv_bfloat16* Al_s = (__nv_bfloat16*)(shraw + 2560);      // 2560 B
    __nv_bfloat16* Bh_s = (__nv_bfloat16*)(shraw + 5120);      // 16896 B
    __nv_bfloat16* Bl_s = (__nv_bfloat16*)(shraw + 22016);     // 16896 B
    int t = threadIdx.x;
    int lane = t & 31, wm = t >> 5;
    const __nv_bfloat16* Ih = I2h + (size_t)b*K*Ntot;
    const __nv_bfloat16* Il = I2l + (size_t)b*K*Ntot;
    int ar = t >> 2, ac = (t & 3)*8;
    bool doA = (t < 128);
    unsigned sAh = smem_u32(Ah_s), sAl = smem_u32(Al_s);
    unsigned sBh = smem_u32(Bh_s), sBl = smem_u32(Bl_s);

    float acc[2][4][4];
    #pragma unroll
    for (int i = 0; i < 2; i++)
        #pragma unroll
        for (int j = 0; j < 4; j++)
            #pragma unroll
            for (int k = 0; k < 4; k++) acc[i][j][k] = 0.f;

    for (int kb = 0; kb < K; kb += 32) {
        uint4 sa_h, sa_l;
        if (doA) {
            sa_h = *(const uint4*)(Wh + (size_t)ar*K + kb + ac);
            sa_l = *(const uint4*)(Wl + (size_t)ar*K + kb + ac);
        }
        uint4 vbh[4], vbl[4];
        #pragma unroll
        for (int j = 0; j < 4; j++) {
            int i = t + 256*j;
            int r = i >> 5, c8 = (i & 31)*8;
            vbh[j] = *(const uint4*)(Ih + (size_t)(kb+r)*Ntot + n0 + c8);
            vbl[j] = *(const uint4*)(Il + (size_t)(kb+r)*Ntot + n0 + c8);
        }
        __syncthreads();
        if (doA) {
            *(uint4*)(Ah_s + ar*GQ_AP + ac) = sa_h;
            *(uint4*)(Al_s + ar*GQ_AP + ac) = sa_l;
        }
        #pragma unroll
        for (int j = 0; j < 4; j++) {
            int i = t + 256*j;
            int r = i >> 5, c8 = (i & 31)*8;
            *(uint4*)(Bh_s + r*GQ_BP + c8) = vbh[j];
            *(uint4*)(Bl_s + r*GQ_BP + c8) = vbl[j];
        }
        __syncthreads();
        #pragma unroll
        for (int kk = 0; kk < 2; kk++) {
            uint32_t bh[2][4], bl[2][4];
            #pragma unroll
            for (int p = 0; p < 2; p++) {
                unsigned off = (unsigned)(((kk*16 + (lane&15))*GQ_BP
                               + wm*32 + p*16 + 8*(lane>>4)) * 2);
                ldmx4t(bh[p], sBh + off);
                ldmx4t(bl[p], sBl + off);
            }
            #pragma unroll
            for (int ct = 0; ct < 2; ct++) {
                unsigned off = (unsigned)(((ct*16 + (lane&15))*GQ_AP
                               + kk*16 + 8*(lane>>4)) * 2);
                uint32_t ah[4], al[4];
                ldmx4(ah, sAh + off);
                ldmx4(al, sAl + off);
                #pragma unroll
                for (int mt = 0; mt < 4; mt++) {
                    const uint32_t* pbh = bh[mt>>1] + (mt&1)*2;
                    const uint32_t* pbl = bl[mt>>1] + (mt&1)*2;
                    mma16816(acc[ct][mt], ah, pbh);
                    mma16816(acc[ct][mt], ah, pbl);
                    mma16816(acc[ct][mt], al, pbh);
                }
            }
        }
    }
    #pragma unroll
    for (int ct = 0; ct < 2; ct++) {
        int r0 = ct*16 + (lane>>2);
        #pragma unroll
        for (int mt = 0; mt < 4; mt++) {
            int col = n0 + wm*32 + mt*8 + 2*(lane&3);
            size_t o0 = ((size_t)(b*CR_) + r0)*Ntot + col;
            __nv_bfloat162 h, l;
            bf16split2(acc[ct][mt][0], acc[ct][mt][1], h, l);
            *(__nv_bfloat162*)(oh + o0) = h;
            *(__nv_bfloat162*)(ol + o0) = l;
            size_t o1 = o0 + (size_t)8*Ntot;
            bf16split2(acc[ct][mt][2], acc[ct][mt][3], h, l);
            *(__nv_bfloat162*)(oh + o1) = h;
            *(__nv_bfloat162*)(ol + o1) = l;
        }
    }
}

__device__ __forceinline__ void cf_softmax_body(char* shraw, int b)
{
    float* red = (float*)shraw;
    int t = threadIdx.x, lane = t & 31, w = t >> 5;
    float v[16];
    #pragma unroll
    for (int i = 0; i < 16; i++) v[i] = g_logit[b*N1_ + t + 256*i];
    float mx = -3e38f;
    #pragma unroll
    for (int i = 0; i < 16; i++) mx = fmaxf(mx, v[i]);
    #pragma unroll
    for (int o = 16; o; o >>= 1) mx = fmaxf(mx, __shfl_xor_sync(~0u, mx, o));
    if (lane == 0) red[w] = mx;
    __syncthreads();
    if (t < 32) {
        float m2 = (t < 8) ? red[t] : -3e38f;
        #pragma unroll
        for (int o = 4; o; o >>= 1) m2 = fmaxf(m2, __shfl_xor_sync(~0u, m2, o));
        red[t] = m2;
    }
    __syncthreads();
    mx = red[0];
    __syncthreads();
    float e[16]; float s = 0.f;
    #pragma unroll
    for (int i = 0; i < 16; i++) { e[i] = fexp(v[i]-mx); s += e[i]; }
    #pragma unroll
    for (int o = 16; o; o >>= 1) s += __shfl_xor_sync(~0u, s, o);
    if (lane == 0) red[w] = s;
    __syncthreads();
    if (t < 32) {
        float s2 = (t < 8) ? red[t] : 0.f;
        #pragma unroll
        for (int o = 4; o; o >>= 1) s2 += __shfl_xor_sync(~0u, s2, o);
        red[t] = s2;
    }
    __syncthreads();
    float inv = 1.f / red[0];
    #pragma unroll
    for (int i = 0; i < 16; i++) g_cf[b*N1_ + t + 256*i] = e[i]*inv;
}

__global__ __launch_bounds__(256) void gemms_k()
{
    __shared__ __align__(16) char shraw[40960];
    int bx = blockIdx.x;
    if (bx < 128) {
        gemm_v_body(shraw, (bx & 7)*128, ((bx >> 3) & 1)*128, bx >> 4);
    } else if (bx < 256) {
        int j = bx - 128;
        gemm_qk_body(shraw, g_wqh, g_wql, g_i2h1, g_i2l1, g_qh, g_ql,
                     KQ_, N1_, (j & 15)*256, j >> 4);
    } else if (bx < 288) {
        int j = bx - 256;
        gemm_qk_body(shraw, g_wkh, g_wkl, g_i2h2, g_i2l2, g_kh, g_kl,
                     KV_, N2_, (j & 3)*256, j >> 2);
    } else {
        cf_softmax_body(shraw, bx - 288);
    }
}

// ============================================================================
// attn_y_k: s_fused (S-GEMM + softmax) | y_k  (block-role dispatch, 512 thr)
// ============================================================================
#define SP_ 1036
#define QP_ 40
#define KP_ 520
#define SF_SMEM (32*SP_*4 + 2*(32*QP_*2) + 2*(32*KP_*2))

__device__ __forceinline__ void s_fused_body(char* smraw, int m0, int b)
{
    float* S_s = (float*)smraw;
    __nv_bfloat16* Qh_s = (__nv_bfloat16*)(smraw + 32*SP_*4);  // [m][c]
    __nv_bfloat16* Ql_s = Qh_s + 32*QP_;
    __nv_bfloat16* Kh_s = Ql_s + 32*QP_;                       // [c][n]
    __nv_bfloat16* Kl_s = Kh_s + 32*KP_;
    int t = threadIdx.x;
    int lane = t & 31, w = t >> 5;           // 16 warps

    if (t < 256) {
        int tt = t & 127;
        int c = tt >> 2, m8 = (tt & 3)*8;
        const __nv_bfloat16* src = (t < 128) ? g_qh : g_ql;
        __nv_bfloat16* dst = (t < 128) ? Qh_s : Ql_s;
        uint4 v = *(const uint4*)(src + ((size_t)(b*CR_ + c))*N1_ + m0 + m8);
        __nv_bfloat16 tmp[8];
        *(uint4*)tmp = v;
        #pragma unroll
        for (int e = 0; e < 8; e++) dst[(m8+e)*QP_ + c] = tmp[e];
    }
    unsigned sQh = smem_u32(Qh_s), sQl = smem_u32(Ql_s);
    unsigned sKh = smem_u32(Kh_s), sKl = smem_u32(Kl_s);

    for (int nb = 0; nb < N2_; nb += 512) {
        uint4 vkh[4], vkl[4];
        #pragma unroll
        for (int j = 0; j < 4; j++) {
            int i = t + 512*j;
            int r = i >> 6, c8 = (i & 63)*8;
            vkh[j] = *(const uint4*)(g_kh + ((size_t)(b*CR_ + r))*N2_ + nb + c8);
            vkl[j] = *(const uint4*)(g_kl + ((size_t)(b*CR_ + r))*N2_ + nb + c8);
        }
        __syncthreads();
        #pragma unroll
        for (int j = 0; j < 4; j++) {
            int i = t + 512*j;
            int r = i >> 6, c8 = (i & 63)*8;
            *(uint4*)(Kh_s + r*KP_ + c8) = vkh[j];
            *(uint4*)(Kl_s + r*KP_ + c8) = vkl[j];
        }
        __syncthreads();
        float acc[2][4][4];
        #pragma unroll
        for (int i = 0; i < 2; i++)
            #pragma unroll
            for (int j = 0; j < 4; j++)
                #pragma unroll
                for (int k = 0; k < 4; k++) acc[i][j][k] = 0.f;
        #pragma unroll
        for (int kk = 0; kk < 2; kk++) {
            uint32_t bh[2][4], bl[2][4];
            #pragma unroll
            for (int p = 0; p < 2; p++) {
                unsigned off = (unsigned)(((kk*16 + (lane&15))*KP_
                               + w*32 + p*16 + 8*(lane>>4)) * 2);
                ldmx4t(bh[p], sKh + off);
                ldmx4t(bl[p], sKl + off);
            }
            #pragma unroll
            for (int ct = 0; ct < 2; ct++) {
                unsigned off = (unsigned)(((ct*16 + (lane&15))*QP_
                               + kk*16 + 8*(lane>>4)) * 2);
                uint32_t ah[4], al[4];
                ldmx4(ah, sQh + off);
                ldmx4(al, sQl + off);
                #pragma unroll
                for (int mt = 0; mt < 4; mt++) {
                    const uint32_t* pbh = bh[mt>>1] + (mt&1)*2;
                    const uint32_t* pbl = bl[mt>>1] + (mt&1)*2;
                    mma16816(acc[ct][mt], ah, pbh);
                    mma16816(acc[ct][mt], ah, pbl);
                    mma16816(acc[ct][mt], al, pbh);
                }
            }
        }
        #pragma unroll
        for (int ct = 0; ct < 2; ct++) {
            int m = ct*16 + (lane>>2);
            #pragma unroll
            for (int mt = 0; mt < 4; mt++) {
                int col = nb + w*32 + mt*8 + 2*(lane&3);
                *(float2*)(S_s + m*SP_ + col) =
                    make_float2(acc[ct][mt][0], acc[ct][mt][1]);
                *(float2*)(S_s + (m+8)*SP_ + col) =
                    make_float2(acc[ct][mt][2], acc[ct][mt][3]);
            }
        }
    }
    __syncthreads();

    // per-row softmax (16 threads per row); emit normalized bf16 P
    {
        int m = t >> 4, g = t & 15;
        float* row = S_s + m*SP_;
        float mx = -3e38f;
        for (int i = g; i < 256; i += 16) {
            float4 v = *(float4*)(row + 4*i);
            mx = fmaxf(mx, fmaxf(fmaxf(v.x, v.y), fmaxf(v.z, v.w)));
        }
        #pragma unroll
        for (int o = 8; o; o >>= 1) mx = fmaxf(mx, __shfl_xor_sync(~0u, mx, o));
        float s = 0.f;
        for (int i = g; i < 256; i += 16) {
            float4 v = *(float4*)(row + 4*i);
            v.x = fexp(v.x - mx); v.y = fexp(v.y - mx);
            v.z = fexp(v.z - mx); v.w = fexp(v.w - mx);
            s += v.x + v.y + v.z + v.w;
            *(float4*)(row + 4*i) = v;
        }
        #pragma unroll
        for (int o = 8; o; o >>= 1) s += __shfl_xor_sync(~0u, s, o);
        float inv = 1.f / s;
        size_t base = ((size_t)(b*N1_) + m0 + m)*N2_;
        for (int i = g; i < 256; i += 16) {
            float4 v = *(float4*)(row + 4*i);
            __nv_bfloat162 h0, h1;
            h0.x = __float2bfloat16_rn(v.x*inv);
            h0.y = __float2bfloat16_rn(v.y*inv);
            h1.x = __float2bfloat16_rn(v.z*inv);
            h1.y = __float2bfloat16_rn(v.w*inv);
            *(__nv_bfloat162*)(g_Ph + base + 4*i)     = h0;
            *(__nv_bfloat162*)(g_Ph + base + 4*i + 2) = h1;
        }
    }
}

__device__ __forceinline__ void y_body(char* smraw, const float* __restrict__ x1,
                                       int i, int b)
{
    float* cf_s = (float*)smraw;                 // 4096 floats
    float* part = (float*)(smraw + 4096*4);      // [16][9]
    int t = threadIdx.x;
    for (int idx = t; idx < N1_; idx += 512) cf_s[idx] = g_cf[b*N1_ + idx];
    __syncthreads();
    float a[9];
    #pragma unroll
    for (int k = 0; k < 9; k++) a[k] = 0.f;
    const float* xp = x1 + ((size_t)(b*C1_ + i))*N1_;
    for (int p = t; p < N1_; p += 512) {
        float xv = xp[p];
        int ph = p >> 6, pw = p & 63;
        #pragma unroll
        for (int dy = 0; dy < 3; dy++) {
            int qh = ph + 1 - dy;
            if ((unsigned)qh < 64u) {
                #pragma unroll
                for (int dx = 0; dx < 3; dx++) {
                    int qw = pw + 1 - dx;
                    if ((unsigned)qw < 64u)
                        a[dy*3+dx] = fmaf(xv, cf_s[(qh<<6)+qw], a[dy*3+dx]);
                }
            }
        }
    }
    #pragma unroll
    for (int k = 0; k < 9; k++) {
        float s = a[k];
        #pragma unroll
        for (int o = 16; o; o >>= 1) s += __shfl_xor_sync(~0u, s, o);
        if ((t&31) == 0) part[(t>>5)*9 + k] = s;
    }
    __syncthreads();
    if (t < 9) {
        float s = 0.f;
        #pragma unroll
        for (int w = 0; w < 16; w++) s += part[w*9 + t];
        g_y[(b*C1_+i)*9 + t] = s;
    }
}

__global__ __launch_bounds__(512) void attn_y_k(const float* __restrict__ x1)
{
    extern __shared__ char smraw[];
    int b = blockIdx.y;
    if (blockIdx.x < 128) s_fused_body(smraw, blockIdx.x*32, b);
    else                  y_body(smraw, x1, blockIdx.x - 128, b);
}

// ---------------- pool = wch*y ; t = wt1*pool ; LN ; relu ; cw = wt2*t -----
__global__ __launch_bounds__(256) void chtail_k(
    const float* __restrict__ wch, const float* __restrict__ wt1,
    const float* __restrict__ bt1, const float* __restrict__ lng,
    const float* __restrict__ lnb, const float* __restrict__ wt2,
    const float* __restrict__ bt2)
{
    __shared__ float y_s[C1_*9];
    __shared__ float pool_s[C1_];
    __shared__ float t_s[CR_];
    int b = blockIdx.x, t = threadIdx.x;
    for (int idx = t; idx < C1_*9; idx += 256) y_s[idx] = g_y[b*C1_*9 + idx];
    __syncthreads();
    {
        float a = 0.f;
        const float* wp = wch + (size_t)t*(C1_*9);
        #pragma unroll 4
        for (int idx = 0; idx < C1_*9; idx++) a = fmaf(wp[idx], y_s[idx], a);
        pool_s[t] = a;
    }
    __syncthreads();
    if (t < CR_) {
        float tv = bt1[t];
        const float* wp = wt1 + t*C1_;
        #pragma unroll 4
        for (int c = 0; c < C1_; c++) tv = fmaf(wp[c], pool_s[c], tv);
        float s1 = tv;
        #pragma unroll
        for (int o = 16; o; o >>= 1) s1 += __shfl_xor_sync(~0u, s1, o);
        float mu = s1 * (1.f/32.f);
        float d  = tv - mu;
        float s2 = d*d;
        #pragma unroll
        for (int o = 16; o; o >>= 1) s2 += __shfl_xor_sync(~0u, s2, o);
        float var = s2 * (1.f/32.f);
        float val = d * rsqrtf(var + 1e-5f) * lng[t] + lnb[t];
        t_s[t] = fmaxf(val, 0.f);
    }
    __syncthreads();
    {
        float a = bt2[t];
        const float* wp = wt2 + t*CR_;
        #pragma unroll
        for (int j = 0; j < CR_; j++) a = fmaf(wp[j], t_s[j], a);
        g_cw[b*C1_ + t] = a;
    }
}

// ---------------- mma.sync O-GEMM: O[c][m] = sum_n V[c][n] P[m][n] --------
// 2-product hi/lo (VhP + VlP); P single bf16.
#define OSTR 40
__global__ __launch_bounds__(256) void o_mma_k(const float* __restrict__ x1,
                                               float* __restrict__ out)
{
    __shared__ __nv_bfloat16 Ah_s[128*OSTR], Al_s[128*OSTR];
    __shared__ __nv_bfloat16 Bh_s[128*OSTR];
    int t = threadIdx.x, b = blockIdx.z;
    int m0 = blockIdx.x*128, c0 = blockIdx.y*128;
    int lane = t & 31, wid = t >> 5;
    int wc = wid >> 2, wm = wid & 3;
    int r = t >> 1, half = t & 1;

    const __nv_bfloat16* srcAh = g_vh + ((size_t)(b*C1_ + c0 + r))*N2_ + half*16;
    const __nv_bfloat16* srcAl = g_vl + ((size_t)(b*C1_ + c0 + r))*N2_ + half*16;
    const __nv_bfloat16* srcBh = g_Ph + ((size_t)(b*N1_ + m0 + r))*N2_ + half*16;
    unsigned dA_h = smem_u32(Ah_s) + (unsigned)((r*OSTR + half*16) * 2);
    unsigned dA_l = smem_u32(Al_s) + (unsigned)((r*OSTR + half*16) * 2);
    unsigned dB_h = smem_u32(Bh_s) + (unsigned)((r*OSTR + half*16) * 2);

    unsigned aAh = smem_u32(Ah_s), aAl = smem_u32(Al_s);
    unsigned aBh = smem_u32(Bh_s);
    int arow = wc*64 + (lane & 15);
    int acol = (lane >> 4) * 8;
    int brow = wm*32 + (lane & 7) + ((lane >> 4) << 3);
    int bcol = ((lane >> 3) & 1) * 8;

    float acc[4][4][4];
    #pragma unroll
    for (int i = 0; i < 4; i++)
        #pragma unroll
        for (int j = 0; j < 4; j++)
            #pragma unroll
            for (int k = 0; k < 4; k++) acc[i][j][k] = 0.f;

    for (int nb = 0; nb < N2_; nb += 32) {
        uint4 vah0 = *(const uint4*)(srcAh + nb);
        uint4 vah1 = *(const uint4*)(srcAh + nb + 8);
        uint4 val0 = *(const uint4*)(srcAl + nb);
        uint4 val1 = *(const uint4*)(srcAl + nb + 8);
        uint4 vbh0 = *(const uint4*)(srcBh + nb);
        uint4 vbh1 = *(const uint4*)(srcBh + nb + 8);
        __syncthreads();
        *(uint4*)(__cvta_shared_to_generic(dA_h))      = vah0;
        *(uint4*)(__cvta_shared_to_generic(dA_h + 16)) = vah1;
        *(uint4*)(__cvta_shared_to_generic(dA_l))      = val0;
        *(uint4*)(__cvta_shared_to_generic(dA_l + 16)) = val1;
        *(uint4*)(__cvta_shared_to_generic(dB_h))      = vbh0;
        *(uint4*)(__cvta_shared_to_generic(dB_h + 16)) = vbh1;
        __syncthreads();
        #pragma unroll
        for (int kk = 0; kk < 2; kk++) {
            int kc = kk*16;
            uint32_t bh[8];
            #pragma unroll
            for (int pair = 0; pair < 2; pair++) {
                unsigned off = (unsigned)(((brow + pair*16)*OSTR + bcol + kc) * 2);
                ldmx4(bh + pair*4, aBh + off);
            }
            #pragma unroll
            for (int ct = 0; ct < 4; ct++) {
                unsigned off = (unsigned)(((arow + ct*16)*OSTR + acol + kc) * 2);
                uint32_t ah[4], al[4];
                ldmx4(ah, aAh + off);
                ldmx4(al, aAl + off);
                #pragma unroll
                for (int mt = 0; mt < 4; mt++) {
                    const uint32_t* pbh = bh + (mt >> 1)*4 + (mt & 1)*2;
                    mma16816(acc[ct][mt], ah, pbh);
                    mma16816(acc[ct][mt], al, pbh);
                }
            }
        }
    }

    int colb = 2*(lane & 3);
    #pragma unroll
    for (int ct = 0; ct < 4; ct++) {
        int cb = c0 + wc*64 + ct*16 + (lane >> 2);
        float cw0 = 1.f + g_cw[b*C1_ + cb];
        float cw1 = 1.f + g_cw[b*C1_ + cb + 8];
        #pragma unroll
        for (int mt = 0; mt < 4; mt++) {
            int m = m0 + wm*32 + mt*8 + colb;
            size_t o0 = ((size_t)(b*C1_ + cb))*N1_ + m;
            size_t o1 = ((size_t)(b*C1_ + cb + 8))*N1_ + m;
            float2 x0 = *(const float2*)(x1 + o0);
            float2 x1v = *(const float2*)(x1 + o1);
            *(float2*)(out + o0) = make_float2(fmaf(x0.x, cw0, acc[ct][mt][0]),
                                               fmaf(x0.y, cw0, acc[ct][mt][1]));
            *(float2*)(out + o1) = make_float2(fmaf(x1v.x, cw1, acc[ct][mt][2]),
                                               fmaf(x1v.y, cw1, acc[ct][mt][3]));
        }
    }
}

// ---------------------------------------------------------------------------
extern "C" void kernel_launch(void* const* d_in, const int* in_sizes, int n_in,
                              void* d_out, int out_size)
{
    (void)in_sizes; (void)n_in; (void)out_size;
    const float* x1  = (const float*)d_in[0];
    const float* x2  = (const float*)d_in[1];
    const float* wq  = (const float*)d_in[2];
    const float* wk  = (const float*)d_in[3];
    const float* wv  = (const float*)d_in[4];
    const float* wc  = (const float*)d_in[5];
    const float* wch = (const float*)d_in[6];
    const float* wt1 = (const float*)d_in[7];
    const float* bt1 = (const float*)d_in[8];
    const float* lng = (const float*)d_in[9];
    const float* lnb = (const float*)d_in[10];
    const float* wt2 = (const float*)d_in[11];
    const float* bt2 = (const float*)d_in[12];
    float* out = (float*)d_out;

    cudaFuncSetAttribute(attn_y_k, cudaFuncAttributeMaxDynamicSharedMemorySize,
                         SF_SMEM);

    // 1) prep: im2col x2/x1, weight splits, cf logits (all concurrent)
    prep_k<<<8160, 256>>>(x1, x2, wq, wk, wv, wc);
    // 2) gemms: conv_v + conv_q + conv_k + cf softmax (all concurrent)
    gemms_k<<<296, 256>>>();
    // 3) fused S-GEMM+softmax and y-pooling (concurrent)
    attn_y_k<<<dim3(384, B_), 512, SF_SMEM>>>(x1);
    // 4) tiny channel tail
    chtail_k<<<B_, 256>>>(wch, wt1, bt1, lng, lnb, wt2, bt2);
    // 5) O-GEMM + fused epilogue
    o_mma_k<<<dim3(N1_/128, C1_/128, B_), 256>>>(x1, out);
}

// round 16
// speedup vs baseline: 1.6077x; 1.1911x over previous
#include <cuda_runtime.h>
#include <cuda_bf16.h>
#include <cstdint>

#define B_ 8
#define C1_ 256
#define C2_ 512
#define H1_ 64
#define W1_ 64
#define N1_ 4096
#define H2_ 32
#define W2_ 32
#define N2_ 1024
#define CR_ 32
#define KQ_ (C1_*9)     // 2304
#define KV_ (C2_*9)     // 4608

// ---------------- scratch (device globals; no allocations) ----------------
__device__ __nv_bfloat16 g_qh[B_*CR_*N1_], g_ql[B_*CR_*N1_];  // q hi/lo [b][c][m]
__device__ __nv_bfloat16 g_kh[B_*CR_*N2_], g_kl[B_*CR_*N2_];  // k hi/lo [b][c][n]
__device__ __nv_bfloat16 g_Ph[B_*N1_*N2_];  // P hi/lo [b][m][n]
__device__ __nv_bfloat16 g_Pl[B_*N1_*N2_];
__device__ __nv_bfloat16 g_vh[B_*C1_*N2_];  // V hi/lo split [b][c][n]
__device__ __nv_bfloat16 g_vl[B_*C1_*N2_];
__device__ __nv_bfloat16 g_i2h1[(size_t)B_*KQ_*N1_];  // im2col(x1) hi/lo
__device__ __nv_bfloat16 g_i2l1[(size_t)B_*KQ_*N1_];
__device__ __nv_bfloat16 g_i2h2[(size_t)B_*KV_*N2_];  // im2col(x2) hi/lo
__device__ __nv_bfloat16 g_i2l2[(size_t)B_*KV_*N2_];
__device__ __nv_bfloat16 g_wvh[C1_*KV_], g_wvl[C1_*KV_];
__device__ __nv_bfloat16 g_wqh[CR_*KQ_], g_wql[CR_*KQ_];
__device__ __nv_bfloat16 g_wkh[CR_*KV_], g_wkl[CR_*KV_];
__device__ float g_logit[B_*N1_];
__device__ float g_cf[B_*N1_];
__device__ float g_y[B_*C1_*9];
__device__ float g_cw[B_*C1_];

// ---------------- helpers -------------------------------------------------
__device__ __forceinline__ uint32_t smem_u32(const void* p) {
    uint32_t a;
    asm("{ .reg .u64 t; cvta.to.shared.u64 t, %1; cvt.u32.u64 %0, t; }"
        : "=r"(a) : "l"(p));
    return a;
}
__device__ __forceinline__ void ldmx4(uint32_t* r, unsigned a) {
    asm volatile("ldmatrix.sync.aligned.m8n8.x4.shared.b16 {%0,%1,%2,%3}, [%4];"
        : "=r"(r[0]), "=r"(r[1]), "=r"(r[2]), "=r"(r[3]) : "r"(a));
}
__device__ __forceinline__ void ldmx4t(uint32_t* r, unsigned a) {
    asm volatile("ldmatrix.sync.aligned.m8n8.x4.trans.shared.b16 {%0,%1,%2,%3}, [%4];"
        : "=r"(r[0]), "=r"(r[1]), "=r"(r[2]), "=r"(r[3]) : "r"(a));
}
__device__ __forceinline__ void mma16816(float* d, const uint32_t* a,
                                         const uint32_t* b) {
    asm volatile(
        "mma.sync.aligned.m16n8k16.row.col.f32.bf16.bf16.f32 "
        "{%0,%1,%2,%3}, {%4,%5,%6,%7}, {%8,%9}, {%0,%1,%2,%3};"
        : "+f"(d[0]), "+f"(d[1]), "+f"(d[2]), "+f"(d[3])
        : "r"(a[0]), "r"(a[1]), "r"(a[2]), "r"(a[3]), "r"(b[0]), "r"(b[1]));
}
__device__ __forceinline__ void bf16split2(float v0, float v1,
                                           __nv_bfloat162& h, __nv_bfloat162& l) {
    h.x = __float2bfloat16_rn(v0); h.y = __float2bfloat16_rn(v1);
    l.x = __float2bfloat16_rn(v0 - __bfloat162float(h.x));
    l.y = __float2bfloat16_rn(v1 - __bfloat162float(h.y));
}

// ---------------- fast exp on FMA pipe ------------------------------------
__device__ __forceinline__ float fexp(float x) {
    x = fmaxf(x, -80.f);
    float t = x * 1.4426950408889634f;
    float z = t + 12582912.f;
    int   i = __float_as_int(z) - 0x4B400000;
    float f = t - (z - 12582912.f);
    float y = f * 0.6931471805599453f;
    float p = 1.f/720.f;
    p = fmaf(p, y, 1.f/120.f);
    p = fmaf(p, y, 1.f/24.f);
    p = fmaf(p, y, 1.f/6.f);
    p = fmaf(p, y, 0.5f);
    p = fmaf(p, y, 1.f);
    p = fmaf(p, y, 1.f);
    return p * __int_as_float((i + 127) << 23);
}

// ============================================================================
// prep_k: im2col2 | im2col1 | wsplit x3 | cf_logit  (block-role dispatch)
// ============================================================================
__device__ __forceinline__ void wsplit_body(const float* __restrict__ w,
                                            __nv_bfloat16* __restrict__ h,
                                            __nv_bfloat16* __restrict__ l,
                                            int i, int n)
{
    if (i >= n) return;
    float v = w[i];
    __nv_bfloat16 hv = __float2bfloat16_rn(v);
    h[i] = hv;
    l[i] = __float2bfloat16_rn(v - __bfloat162float(hv));
}

__global__ __launch_bounds__(256) void prep_k(
    const float* __restrict__ x1, const float* __restrict__ x2,
    const float* __restrict__ wq, const float* __restrict__ wk,
    const float* __restrict__ wv, const float* __restrict__ wc)
{
    __shared__ float sh[8*1024];
    int bx = blockIdx.x, t = threadIdx.x;

    if (bx < 512) {                       // ---- im2col2 (x2 32x32) ----
        int cig = bx & 63, b = bx >> 6;
        const float* src = x2 + ((size_t)(b*C2_ + cig*8))*N2_;
        for (int i = t; i < 8*1024; i += 256) sh[i] = src[i];
        __syncthreads();
        #pragma unroll
        for (int ci = 0; ci < 8; ci++) {
            size_t kbase = (size_t)b*KV_ + (size_t)(cig*8+ci)*9;
            #pragma unroll
            for (int j = 0; j < 9; j++) {
                int dy = j/3 - 1, dx = j%3 - 1;
                size_t dst = (kbase + j)*N2_;
                #pragma unroll
                for (int rep = 0; rep < 2; rep++) {
                    int n = 2*(t + 256*rep);
                    int h = n >> 5, w = n & 31;
                    int shh = h + dy;
                    float v0 = 0.f, v1 = 0.f;
                    if ((unsigned)shh < 32u) {
                        int sw0 = w + dx;
                        if ((unsigned)sw0 < 32u) v0 = sh[ci*1024 + (shh<<5) + sw0];
                        if ((unsigned)(sw0+1) < 32u) v1 = sh[ci*1024 + (shh<<5) + sw0 + 1];
                    }
                    __nv_bfloat162 hh, ll;
                    bf16split2(v0, v1, hh, ll);
                    *(__nv_bfloat162*)(g_i2h2 + dst + n) = hh;
                    *(__nv_bfloat162*)(g_i2l2 + dst + n) = ll;
                }
            }
        }
    } else if (bx < 2560) {               // ---- im2col1 (x1 64x64) ----
        int j0 = bx - 512;
        int ci = j0 & 255, b = j0 >> 8;
        const float* src = x1 + ((size_t)(b*C1_ + ci))*N1_;
        for (int i = t; i < 4096; i += 256) sh[i] = src[i];
        __syncthreads();
        size_t kbase = (size_t)b*KQ_ + (size_t)ci*9;
        #pragma unroll
        for (int j = 0; j < 9; j++) {
            int dy = j/3 - 1, dx = j%3 - 1;
            size_t dst = (kbase + j)*N1_;
            #pragma unroll
            for (int rep = 0; rep < 8; rep++) {
                int n = 2*(t + 256*rep);
                int h = n >> 6, w = n & 63;
                int shh = h + dy;
                float v0 = 0.f, v1 = 0.f;
                if ((unsigned)shh < 64u) {
                    int sw0 = w + dx;
                    if ((unsigned)sw0 < 64u) v0 = sh[(shh<<6) + sw0];
                    if ((unsigned)(sw0+1) < 64u) v1 = sh[(shh<<6) + sw0 + 1];
                }
                __nv_bfloat162 hh, ll;
                bf16split2(v0, v1, hh, ll);
                *(__nv_bfloat162*)(g_i2h1 + dst + n) = hh;
                *(__nv_bfloat162*)(g_i2l1 + dst + n) = ll;
            }
        }
    } else if (bx < 7168) {               // ---- wsplit wv ----
        wsplit_body(wv, g_wvh, g_wvl, (bx-2560)*256 + t, C1_*KV_);
    } else if (bx < 7456) {               // ---- wsplit wq ----
        wsplit_body(wq, g_wqh, g_wql, (bx-7168)*256 + t, CR_*KQ_);
    } else if (bx < 8032) {               // ---- wsplit wk ----
        wsplit_body(wk, g_wkh, g_wkl, (bx-7456)*256 + t, CR_*KV_);
    } else {                              // ---- cf_logit ----
        int j0 = bx - 8032;
        int nblk = j0 & 15, b = j0 >> 4;
        float* wc_s = sh;
        wc_s[t] = wc[t];
        __syncthreads();
        int n = nblk*256 + t;
        const float* xp = x1 + (size_t)b*C1_*N1_ + n;
        float s0 = 0.f, s1 = 0.f, s2 = 0.f, s3 = 0.f;
        #pragma unroll 4
        for (int c = 0; c < C1_; c += 4) {
            s0 = fmaf(wc_s[c+0], __ldg(xp + (size_t)(c+0)*N1_), s0);
            s1 = fmaf(wc_s[c+1], __ldg(xp + (size_t)(c+1)*N1_), s1);
            s2 = fmaf(wc_s[c+2], __ldg(xp + (size_t)(c+2)*N1_), s2);
            s3 = fmaf(wc_s[c+3], __ldg(xp + (size_t)(c+3)*N1_), s3);
        }
        g_logit[b*N1_ + n] = (s0 + s1) + (s2 + s3);
    }
}

// ============================================================================
// gemms_k: gemm_v | gemm_q | gemm_k | cf_softmax  (block-role dispatch)
// ============================================================================
#define GV_AP 40
#define GV_BP 136
__device__ __forceinline__ void gemm_v_body(char* shraw, int n0, int co0, int b)
{
    __nv_bfloat16* Ah_s = (__nv_bfloat16*)shraw;               // 10240 B
    __nv_bfloat16* Al_s = (__nv_bfloat16*)(shraw + 10240);     // 10240 B
    __nv_bfloat16* Bh_s = (__nv_bfloat16*)(shraw + 20480);     // 8704 B
    __nv_bfloat16* Bl_s = (__nv_bfloat16*)(shraw + 29184);     // 8704 B
    const int K = KV_;
    int t = threadIdx.x;
    int lane = t & 31, wid = t >> 5;
    int wc = wid >> 2, wm = wid & 3;

    const __nv_bfloat16* Ih = g_i2h2 + (size_t)b*K*N2_;
    const __nv_bfloat16* Il = g_i2l2 + (size_t)b*K*N2_;
    int ar = t >> 2, ac = (t & 3) * 8;
    int br = t >> 4, bc = (t & 15) * 8;
    unsigned sAh = smem_u32(Ah_s), sAl = smem_u32(Al_s);
    unsigned sBh = smem_u32(Bh_s), sBl = smem_u32(Bl_s);

    float acc[4][4][4];
    #pragma unroll
    for (int i = 0; i < 4; i++)
        #pragma unroll
        for (int j = 0; j < 4; j++)
            #pragma unroll
            for (int k = 0; k < 4; k++) acc[i][j][k] = 0.f;

    for (int kb = 0; kb < K; kb += 32) {
        uint4 vah0 = *(const uint4*)(g_wvh + (size_t)(co0+ar)*K + kb + ac);
        uint4 vah1 = *(const uint4*)(g_wvh + (size_t)(co0+ar+64)*K + kb + ac);
        uint4 val0 = *(const uint4*)(g_wvl + (size_t)(co0+ar)*K + kb + ac);
        uint4 val1 = *(const uint4*)(g_wvl + (size_t)(co0+ar+64)*K + kb + ac);
        uint4 vbh0 = *(const uint4*)(Ih + (size_t)(kb+br)*N2_ + n0 + bc);
        uint4 vbh1 = *(const uint4*)(Ih + (size_t)(kb+br+16)*N2_ + n0 + bc);
        uint4 vbl0 = *(const uint4*)(Il + (size_t)(kb+br)*N2_ + n0 + bc);
        uint4 vbl1 = *(const uint4*)(Il + (size_t)(kb+br+16)*N2_ + n0 + bc);
        __syncthreads();
        *(uint4*)(Ah_s + ar*GV_AP + ac)      = vah0;
        *(uint4*)(Ah_s + (ar+64)*GV_AP + ac) = vah1;
        *(uint4*)(Al_s + ar*GV_AP + ac)      = val0;
        *(uint4*)(Al_s + (ar+64)*GV_AP + ac) = val1;
        *(uint4*)(Bh_s + br*GV_BP + bc)      = vbh0;
        *(uint4*)(Bh_s + (br+16)*GV_BP + bc) = vbh1;
        *(uint4*)(Bl_s + br*GV_BP + bc)      = vbl0;
        *(uint4*)(Bl_s + (br+16)*GV_BP + bc) = vbl1;
        __syncthreads();
        #pragma unroll
        for (int kk = 0; kk < 2; kk++) {
            uint32_t bh[2][4], bl[2][4];
            #pragma unroll
            for (int p = 0; p < 2; p++) {
                unsigned off = (unsigned)(((kk*16 + (lane&15))*GV_BP
                               + wm*32 + p*16 + 8*(lane>>4)) * 2);
                ldmx4t(bh[p], sBh + off);
                ldmx4t(bl[p], sBl + off);
            }
            #pragma unroll
            for (int ct = 0; ct < 4; ct++) {
                unsigned off = (unsigned)(((wc*64 + ct*16 + (lane&15))*GV_AP
                               + kk*16 + 8*(lane>>4)) * 2);
                uint32_t ah[4], al[4];
                ldmx4(ah, sAh + off);
                ldmx4(al, sAl + off);
                #pragma unroll
                for (int mt = 0; mt < 4; mt++) {
                    const uint32_t* pbh = bh[mt>>1] + (mt&1)*2;
                    const uint32_t* pbl = bl[mt>>1] + (mt&1)*2;
                    mma16816(acc[ct][mt], ah, pbh);
                    mma16816(acc[ct][mt], ah, pbl);
                    mma16816(acc[ct][mt], al, pbh);
                }
            }
        }
    }
    #pragma unroll
    for (int ct = 0; ct < 4; ct++) {
        int r0 = co0 + wc*64 + ct*16 + (lane>>2);
        #pragma unroll
        for (int mt = 0; mt < 4; mt++) {
            int col = n0 + wm*32 + mt*8 + 2*(lane&3);
            size_t o0 = ((size_t)(b*C1_) + r0)*N2_ + col;
            __nv_bfloat162 h, l;
            bf16split2(acc[ct][mt][0], acc[ct][mt][1], h, l);
            *(__nv_bfloat162*)(g_vh + o0) = h;
            *(__nv_bfloat162*)(g_vl + o0) = l;
            size_t o1 = o0 + (size_t)8*N2_;
            bf16split2(acc[ct][mt][2], acc[ct][mt][3], h, l);
            *(__nv_bfloat162*)(g_vh + o1) = h;
            *(__nv_bfloat162*)(g_vl + o1) = l;
        }
    }
}

#define GQ_AP 40
#define GQ_BP 264
__device__ __forceinline__ void gemm_qk_body(char* shraw,
    const __nv_bfloat16* __restrict__ Wh, const __nv_bfloat16* __restrict__ Wl,
    const __nv_bfloat16* __restrict__ I2h, const __nv_bfloat16* __restrict__ I2l,
    __nv_bfloat16* __restrict__ oh, __nv_bfloat16* __restrict__ ol,
    int K, int Ntot, int n0, int b)
{
    __nv_bfloat16* Ah_s = (__nv_bfloat16*)shraw;               // 2560 B
    __nv_bfloat16* Al_s = (__nv_bfloat16*)(shraw + 2560);      // 2560 B
    __nv_bfloat16* Bh_s = (__nv_bfloat16*)(shraw + 5120);      // 16896 B
    __nv_bfloat16* Bl_s = (__nv_bfloat16*)(shraw + 22016);     // 16896 B
    int t = threadIdx.x;
    int lane = t & 31, wm = t >> 5;
    const __nv_bfloat16* Ih = I2h + (size_t)b*K*Ntot;
    const __nv_bfloat16* Il = I2l + (size_t)b*K*Ntot;
    int ar = t >> 2, ac = (t & 3)*8;
    bool doA = (t < 128);
    unsigned sAh = smem_u32(Ah_s), sAl = smem_u32(Al_s);
    unsigned sBh = smem_u32(Bh_s), sBl = smem_u32(Bl_s);

    float acc[2][4][4];
    #pragma unroll
    for (int i = 0; i < 2; i++)
        #pragma unroll
        for (int j = 0; j < 4; j++)
            #pragma unroll
            for (int k = 0; k < 4; k++) acc[i][j][k] = 0.f;

    for (int kb = 0; kb < K; kb += 32) {
        uint4 sa_h, sa_l;
        if (doA) {
            sa_h = *(const uint4*)(Wh + (size_t)ar*K + kb + ac);
            sa_l = *(const uint4*)(Wl + (size_t)ar*K + kb + ac);
        }
        uint4 vbh[4], vbl[4];
        #pragma unroll
        for (int j = 0; j < 4; j++) {
            int i = t + 256*j;
            int r = i >> 5, c8 = (i & 31)*8;
            vbh[j] = *(const uint4*)(Ih + (size_t)(kb+r)*Ntot + n0 + c8);
            vbl[j] = *(const uint4*)(Il + (size_t)(kb+r)*Ntot + n0 + c8);
        }
        __syncthreads();
        if (doA) {
            *(uint4*)(Ah_s + ar*GQ_AP + ac) = sa_h;
            *(uint4*)(Al_s + ar*GQ_AP + ac) = sa_l;
        }
        #pragma unroll
        for (int j = 0; j < 4; j++) {
            int i = t + 256*j;
            int r = i >> 5, c8 = (i & 31)*8;
            *(uint4*)(Bh_s + r*GQ_BP + c8) = vbh[j];
            *(uint4*)(Bl_s + r*GQ_BP + c8) = vbl[j];
        }
        __syncthreads();
        #pragma unroll
        for (int kk = 0; kk < 2; kk++) {
            uint32_t bh[2][4], bl[2][4];
            #pragma unroll
            for (int p = 0; p < 2; p++) {
                unsigned off = (unsigned)(((kk*16 + (lane&15))*GQ_BP
                               + wm*32 + p*16 + 8*(lane>>4)) * 2);
                ldmx4t(bh[p], sBh + off);
                ldmx4t(bl[p], sBl + off);
            }
            #pragma unroll
            for (int ct = 0; ct < 2; ct++) {
                unsigned off = (unsigned)(((ct*16 + (lane&15))*GQ_AP
                               + kk*16 + 8*(lane>>4)) * 2);
                uint32_t ah[4], al[4];
                ldmx4(ah, sAh + off);
                ldmx4(al, sAl + off);
                #pragma unroll
                for (int mt = 0; mt < 4; mt++) {
                    const uint32_t* pbh = bh[mt>>1] + (mt&1)*2;
                    const uint32_t* pbl = bl[mt>>1] + (mt&1)*2;
                    mma16816(acc[ct][mt], ah, pbh);
                    mma16816(acc[ct][mt], ah, pbl);
                    mma16816(acc[ct][mt], al, pbh);
                }
            }
        }
    }
    #pragma unroll
    for (int ct = 0; ct < 2; ct++) {
        int r0 = ct*16 + (lane>>2);
        #pragma unroll
        for (int mt = 0; mt < 4; mt++) {
            int col = n0 + wm*32 + mt*8 + 2*(lane&3);
            size_t o0 = ((size_t)(b*CR_) + r0)*Ntot + col;
            __nv_bfloat162 h, l;
            bf16split2(acc[ct][mt][0], acc[ct][mt][1], h, l);
            *(__nv_bfloat162*)(oh + o0) = h;
            *(__nv_bfloat162*)(ol + o0) = l;
            size_t o1 = o0 + (size_t)8*Ntot;
            bf16split2(acc[ct][mt][2], acc[ct][mt][3], h, l);
            *(__nv_bfloat162*)(oh + o1) = h;
            *(__nv_bfloat162*)(ol + o1) = l;
        }
    }
}

__device__ __forceinline__ void cf_softmax_body(char* shraw, int b)
{
    float* red = (float*)shraw;
    int t = threadIdx.x, lane = t & 31, w = t >> 5;
    float v[16];
    #pragma unroll
    for (int i = 0; i < 16; i++) v[i] = g_logit[b*N1_ + t + 256*i];
    float mx = -3e38f;
    #pragma unroll
    for (int i = 0; i < 16; i++) mx = fmaxf(mx, v[i]);
    #pragma unroll
    for (int o = 16; o; o >>= 1) mx = fmaxf(mx, __shfl_xor_sync(~0u, mx, o));
    if (lane == 0) red[w] = mx;
    __syncthreads();
    if (t < 32) {
        float m2 = (t < 8) ? red[t] : -3e38f;
        #pragma unroll
        for (int o = 4; o; o >>= 1) m2 = fmaxf(m2, __shfl_xor_sync(~0u, m2, o));
        red[t] = m2;
    }
    __syncthreads();
    mx = red[0];
    __syncthreads();
    float e[16]; float s = 0.f;
    #pragma unroll
    for (int i = 0; i < 16; i++) { e[i] = fexp(v[i]-mx); s += e[i]; }
    #pragma unroll
    for (int o = 16; o; o >>= 1) s += __shfl_xor_sync(~0u, s, o);
    if (lane == 0) red[w] = s;
    __syncthreads();
    if (t < 32) {
        float s2 = (t < 8) ? red[t] : 0.f;
        #pragma unroll
        for (int o = 4; o; o >>= 1) s2 += __shfl_xor_sync(~0u, s2, o);
        red[t] = s2;
    }
    __syncthreads();
    float inv = 1.f / red[0];
    #pragma unroll
    for (int i = 0; i < 16; i++) g_cf[b*N1_ + t + 256*i] = e[i]*inv;
}

__global__ __launch_bounds__(256) void gemms_k()
{
    __shared__ __align__(16) char shraw[40960];
    int bx = blockIdx.x;
    if (bx < 128) {
        gemm_v_body(shraw, (bx & 7)*128, ((bx >> 3) & 1)*128, bx >> 4);
    } else if (bx < 256) {
        int j = bx - 128;
        gemm_qk_body(shraw, g_wqh, g_wql, g_i2h1, g_i2l1, g_qh, g_ql,
                     KQ_, N1_, (j & 15)*256, j >> 4);
    } else if (bx < 288) {
        int j = bx - 256;
        gemm_qk_body(shraw, g_wkh, g_wkl, g_i2h2, g_i2l2, g_kh, g_kl,
                     KV_, N2_, (j & 3)*256, j >> 2);
    } else {
        cf_softmax_body(shraw, bx - 288);
    }
}

// ============================================================================
// attn_y_k: s_fused (S-GEMM + softmax) | y_k  (block-role dispatch, 512 thr)
// ============================================================================
#define SP_ 1036
#define QP_ 40
#define KP_ 520
#define SF_SMEM (32*SP_*4 + 2*(32*QP_*2) + 2*(32*KP_*2))

__device__ __forceinline__ void s_fused_body(char* smraw, int m0, int b)
{
    float* S_s = (float*)smraw;
    __nv_bfloat16* Qh_s = (__nv_bfloat16*)(smraw + 32*SP_*4);  // [m][c]
    __nv_bfloat16* Ql_s = Qh_s + 32*QP_;
    __nv_bfloat16* Kh_s = Ql_s + 32*QP_;                       // [c][n]
    __nv_bfloat16* Kl_s = Kh_s + 32*KP_;
    int t = threadIdx.x;
    int lane = t & 31, w = t >> 5;           // 16 warps

    if (t < 256) {
        int tt = t & 127;
        int c = tt >> 2, m8 = (tt & 3)*8;
        const __nv_bfloat16* src = (t < 128) ? g_qh : g_ql;
        __nv_bfloat16* dst = (t < 128) ? Qh_s : Ql_s;
        uint4 v = *(const uint4*)(src + ((size_t)(b*CR_ + c))*N1_ + m0 + m8);
        __nv_bfloat16 tmp[8];
        *(uint4*)tmp = v;
        #pragma unroll
        for (int e = 0; e < 8; e++) dst[(m8+e)*QP_ + c] = tmp[e];
    }
    unsigned sQh = smem_u32(Qh_s), sQl = smem_u32(Ql_s);
    unsigned sKh = smem_u32(Kh_s), sKl = smem_u32(Kl_s);

    for (int nb = 0; nb < N2_; nb += 512) {
        uint4 vkh[4], vkl[4];
        #pragma unroll
        for (int j = 0; j < 4; j++) {
            int i = t + 512*j;
            int r = i >> 6, c8 = (i & 63)*8;
            vkh[j] = *(const uint4*)(g_kh + ((size_t)(b*CR_ + r))*N2_ + nb + c8);
            vkl[j] = *(const uint4*)(g_kl + ((size_t)(b*CR_ + r))*N2_ + nb + c8);
        }
        __syncthreads();
        #pragma unroll
        for (int j = 0; j < 4; j++) {
            int i = t + 512*j;
            int r = i >> 6, c8 = (i & 63)*8;
            *(uint4*)(Kh_s + r*KP_ + c8) = vkh[j];
            *(uint4*)(Kl_s + r*KP_ + c8) = vkl[j];
        }
        __syncthreads();
        float acc[2][4][4];
        #pragma unroll
        for (int i = 0; i < 2; i++)
            #pragma unroll
            for (int j = 0; j < 4; j++)
                #pragma unroll
                for (int k = 0; k < 4; k++) acc[i][j][k] = 0.f;
        #pragma unroll
        for (int kk = 0; kk < 2; kk++) {
            uint32_t bh[2][4], bl[2][4];
            #pragma unroll
            for (int p = 0; p < 2; p++) {
                unsigned off = (unsigned)(((kk*16 + (lane&15))*KP_
                               + w*32 + p*16 + 8*(lane>>4)) * 2);
                ldmx4t(bh[p], sKh + off);
                ldmx4t(bl[p], sKl + off);
            }
            #pragma unroll
            for (int ct = 0; ct < 2; ct++) {
                unsigned off = (unsigned)(((ct*16 + (lane&15))*QP_
                               + kk*16 + 8*(lane>>4)) * 2);
                uint32_t ah[4], al[4];
                ldmx4(ah, sQh + off);
                ldmx4(al, sQl + off);
                #pragma unroll
                for (int mt = 0; mt < 4; mt++) {
                    const uint32_t* pbh = bh[mt>>1] + (mt&1)*2;
                    const uint32_t* pbl = bl[mt>>1] + (mt&1)*2;
                    mma16816(acc[ct][mt], ah, pbh);
                    mma16816(acc[ct][mt], ah, pbl);
                    mma16816(acc[ct][mt], al, pbh);
                }
            }
        }
        #pragma unroll
        for (int ct = 0; ct < 2; ct++) {
            int m = ct*16 + (lane>>2);
            #pragma unroll
            for (int mt = 0; mt < 4; mt++) {
                int col = nb + w*32 + mt*8 + 2*(lane&3);
                *(float2*)(S_s + m*SP_ + col) =
                    make_float2(acc[ct][mt][0], acc[ct][mt][1]);
                *(float2*)(S_s + (m+8)*SP_ + col) =
                    make_float2(acc[ct][mt][2], acc[ct][mt][3]);
            }
        }
    }
    __syncthreads();

    // per-row softmax (16 threads per row); emit P bf16 hi/lo
    {
        int m = t >> 4, g = t & 15;
        float* row = S_s + m*SP_;
        float mx = -3e38f;
        for (int i = g; i < 256; i += 16) {
            float4 v = *(float4*)(row + 4*i);
            mx = fmaxf(mx, fmaxf(fmaxf(v.x, v.y), fmaxf(v.z, v.w)));
        }
        #pragma unroll
        for (int o = 8; o; o >>= 1) mx = fmaxf(mx, __shfl_xor_sync(~0u, mx, o));
        float s = 0.f;
        for (int i = g; i < 256; i += 16) {
            float4 v = *(float4*)(row + 4*i);
            v.x = fexp(v.x - mx); v.y = fexp(v.y - mx);
            v.z = fexp(v.z - mx); v.w = fexp(v.w - mx);
            s += v.x + v.y + v.z + v.w;
            *(float4*)(row + 4*i) = v;
        }
        #pragma unroll
        for (int o = 8; o; o >>= 1) s += __shfl_xor_sync(~0u, s, o);
        float inv = 1.f / s;
        size_t base = ((size_t)(b*N1_) + m0 + m)*N2_;
        for (int i = g; i < 256; i += 16) {
            float4 v = *(float4*)(row + 4*i);
            __nv_bfloat162 h0, h1, l0, l1;
            bf16split2(v.x*inv, v.y*inv, h0, l0);
            bf16split2(v.z*inv, v.w*inv, h1, l1);
            *(__nv_bfloat162*)(g_Ph + base + 4*i)     = h0;
            *(__nv_bfloat162*)(g_Ph + base + 4*i + 2) = h1;
            *(__nv_bfloat162*)(g_Pl + base + 4*i)     = l0;
            *(__nv_bfloat162*)(g_Pl + base + 4*i + 2) = l1;
        }
    }
}

__device__ __forceinline__ void y_body(char* smraw, const float* __restrict__ x1,
                                       int i, int b)
{
    float* cf_s = (float*)smraw;                 // 4096 floats
    float* part = (float*)(smraw + 4096*4);      // [16][9]
    int t = threadIdx.x;
    for (int idx = t; idx < N1_; idx += 512) cf_s[idx] = g_cf[b*N1_ + idx];
    __syncthreads();
    float a[9];
    #pragma unroll
    for (int k = 0; k < 9; k++) a[k] = 0.f;
    const float* xp = x1 + ((size_t)(b*C1_ + i))*N1_;
    for (int p = t; p < N1_; p += 512) {
        float xv = xp[p];
        int ph = p >> 6, pw = p & 63;
        #pragma unroll
        for (int dy = 0; dy < 3; dy++) {
            int qh = ph + 1 - dy;
            if ((unsigned)qh < 64u) {
                #pragma unroll
                for (int dx = 0; dx < 3; dx++) {
                    int qw = pw + 1 - dx;
                    if ((unsigned)qw < 64u)
                        a[dy*3+dx] = fmaf(xv, cf_s[(qh<<6)+qw], a[dy*3+dx]);
                }
            }
        }
    }
    #pragma unroll
    for (int k = 0; k < 9; k++) {
        float s = a[k];
        #pragma unroll
        for (int o = 16; o; o >>= 1) s += __shfl_xor_sync(~0u, s, o);
        if ((t&31) == 0) part[(t>>5)*9 + k] = s;
    }
    __syncthreads();
    if (t < 9) {
        float s = 0.f;
        #pragma unroll
        for (int w = 0; w < 16; w++) s += part[w*9 + t];
        g_y[(b*C1_+i)*9 + t] = s;
    }
}

__global__ __launch_bounds__(512) void attn_y_k(const float* __restrict__ x1)
{
    extern __shared__ char smraw[];
    int b = blockIdx.y;
    if (blockIdx.x < 128) s_fused_body(smraw, blockIdx.x*32, b);
    else                  y_body(smraw, x1, blockIdx.x - 128, b);
}

// ---------------- chtail: coalesced warp-per-channel GEMVs -----------------
__global__ __launch_bounds__(256) void chtail_k(
    const float* __restrict__ wch, const float* __restrict__ wt1,
    const float* __restrict__ bt1, const float* __restrict__ lng,
    const float* __restrict__ lnb, const float* __restrict__ wt2,
    const float* __restrict__ bt2)
{
    __shared__ float y_s[C1_*9];
    __shared__ float pool_s[C1_];
    __shared__ float tpre[CR_];
    __shared__ float t_s[CR_];
    int b = blockIdx.x, t = threadIdx.x;
    int lane = t & 31, wid = t >> 5;
    for (int idx = t; idx < C1_*9; idx += 256) y_s[idx] = g_y[b*C1_*9 + idx];
    __syncthreads();
    // pool[c] = dot(wch[c,:], y_s)  — warp per channel, coalesced
    for (int c = wid; c < C1_; c += 8) {
        const float* wp = wch + (size_t)c*(C1_*9);
        float a = 0.f;
        for (int i = lane; i < C1_*9; i += 32) a = fmaf(wp[i], y_s[i], a);
        #pragma unroll
        for (int o = 16; o; o >>= 1) a += __shfl_xor_sync(~0u, a, o);
        if (lane == 0) pool_s[c] = a;
    }
    __syncthreads();
    // tpre[r] = dot(wt1[r,:], pool) + bt1[r] — warp per row, coalesced
    #pragma unroll
    for (int rr = 0; rr < 4; rr++) {
        int r = wid*4 + rr;
        const float* wp = wt1 + r*C1_;
        float a = 0.f;
        #pragma unroll
        for (int i = 0; i < 8; i++) a = fmaf(wp[lane + 32*i], pool_s[lane + 32*i], a);
        #pragma unroll
        for (int o = 16; o; o >>= 1) a += __shfl_xor_sync(~0u, a, o);
        if (lane == 0) tpre[r] = a + bt1[r];
    }
    __syncthreads();
    if (t < CR_) {
        float tv = tpre[t];
        float s1 = tv;
        #pragma unroll
        for (int o = 16; o; o >>= 1) s1 += __shfl_xor_sync(~0u, s1, o);
        float mu = s1 * (1.f/32.f);
        float d  = tv - mu;
        float s2 = d*d;
        #pragma unroll
        for (int o = 16; o; o >>= 1) s2 += __shfl_xor_sync(~0u, s2, o);
        float var = s2 * (1.f/32.f);
        float val = d * rsqrtf(var + 1e-5f) * lng[t] + lnb[t];
        t_s[t] = fmaxf(val, 0.f);
    }
    __syncthreads();
    {
        float a = bt2[t];
        const float* wp = wt2 + t*CR_;
        #pragma unroll
        for (int j = 0; j < CR_; j++) a = fmaf(wp[j], t_s[j], a);
        g_cw[b*C1_ + t] = a;
    }
}

// ---------------- mma.sync O-GEMM: 3-product hi/lo (VhPh+VhPl+VlPh) -------
#define OSTR 40
__global__ __launch_bounds__(256) void o_mma_k(const float* __restrict__ x1,
                                               float* __restrict__ out)
{
    __shared__ __nv_bfloat16 Ah_s[128*OSTR], Al_s[128*OSTR];
    __shared__ __nv_bfloat16 Bh_s[128*OSTR], Bl_s[128*OSTR];
    int t = threadIdx.x, b = blockIdx.z;
    int m0 = blockIdx.x*128, c0 = blockIdx.y*128;
    int lane = t & 31, wid = t >> 5;
    int wc = wid >> 2, wm = wid & 3;
    int r = t >> 1, half = t & 1;

    const __nv_bfloat16* srcAh = g_vh + ((size_t)(b*C1_ + c0 + r))*N2_ + half*16;
    const __nv_bfloat16* srcAl = g_vl + ((size_t)(b*C1_ + c0 + r))*N2_ + half*16;
    const __nv_bfloat16* srcBh = g_Ph + ((size_t)(b*N1_ + m0 + r))*N2_ + half*16;
    const __nv_bfloat16* srcBl = g_Pl + ((size_t)(b*N1_ + m0 + r))*N2_ + half*16;
    unsigned dA_h = smem_u32(Ah_s) + (unsigned)((r*OSTR + half*16) * 2);
    unsigned dA_l = smem_u32(Al_s) + (unsigned)((r*OSTR + half*16) * 2);
    unsigned dB_h = smem_u32(Bh_s) + (unsigned)((r*OSTR + half*16) * 2);
    unsigned dB_l = smem_u32(Bl_s) + (unsigned)((r*OSTR + half*16) * 2);

    unsigned aAh = smem_u32(Ah_s), aAl = smem_u32(Al_s);
    unsigned aBh = smem_u32(Bh_s), aBl = smem_u32(Bl_s);
    int arow = wc*64 + (lane & 15);
    int acol = (lane >> 4) * 8;
    int brow = wm*32 + (lane & 7) + ((lane >> 4) << 3);
    int bcol = ((lane >> 3) & 1) * 8;

    float acc[4][4][4];
    #pragma unroll
    for (int i = 0; i < 4; i++)
        #pragma unroll
        for (int j = 0; j < 4; j++)
            #pragma unroll
            for (int k = 0; k < 4; k++) acc[i][j][k] = 0.f;

    for (int nb = 0; nb < N2_; nb += 32) {
        uint4 vah0 = *(const uint4*)(srcAh + nb);
        uint4 vah1 = *(const uint4*)(srcAh + nb + 8);
        uint4 val0 = *(const uint4*)(srcAl + nb);
        uint4 val1 = *(const uint4*)(srcAl + nb + 8);
        uint4 vbh0 = *(const uint4*)(srcBh + nb);
        uint4 vbh1 = *(const uint4*)(srcBh + nb + 8);
        uint4 vbl0 = *(const uint4*)(srcBl + nb);
        uint4 vbl1 = *(const uint4*)(srcBl + nb + 8);
        __syncthreads();
        *(uint4*)(__cvta_shared_to_generic(dA_h))      = vah0;
        *(uint4*)(__cvta_shared_to_generic(dA_h + 16)) = vah1;
        *(uint4*)(__cvta_shared_to_generic(dA_l))      = val0;
        *(uint4*)(__cvta_shared_to_generic(dA_l + 16)) = val1;
        *(uint4*)(__cvta_shared_to_generic(dB_h))      = vbh0;
        *(uint4*)(__cvta_shared_to_generic(dB_h + 16)) = vbh1;
        *(uint4*)(__cvta_shared_to_generic(dB_l))      = vbl0;
        *(uint4*)(__cvta_shared_to_generic(dB_l + 16)) = vbl1;
        __syncthreads();
        #pragma unroll
        for (int kk = 0; kk < 2; kk++) {
            int kc = kk*16;
            uint32_t bh[8], bl[8];
            #pragma unroll
            for (int pair = 0; pair < 2; pair++) {
                unsigned off = (unsigned)(((brow + pair*16)*OSTR + bcol + kc) * 2);
                ldmx4(bh + pair*4, aBh + off);
                ldmx4(bl + pair*4, aBl + off);
            }
            #pragma unroll
            for (int ct = 0; ct < 4; ct++) {
                unsigned off = (unsigned)(((arow + ct*16)*OSTR + acol + kc) * 2);
                uint32_t ah[4], al[4];
                ldmx4(ah, aAh + off);
                ldmx4(al, aAl + off);
                #pragma unroll
                for (int mt = 0; mt < 4; mt++) {
                    const uint32_t* pbh = bh + (mt >> 1)*4 + (mt & 1)*2;
                    const uint32_t* pbl = bl + (mt >> 1)*4 + (mt & 1)*2;
                    mma16816(acc[ct][mt], ah, pbh);
                    mma16816(acc[ct][mt], ah, pbl);
                    mma16816(acc[ct][mt], al, pbh);
                }
            }
        }
    }

    int colb = 2*(lane & 3);
    #pragma unroll
    for (int ct = 0; ct < 4; ct++) {
        int cb = c0 + wc*64 + ct*16 + (lane >> 2);
        float cw0 = 1.f + g_cw[b*C1_ + cb];
        float cw1 = 1.f + g_cw[b*C1_ + cb + 8];
        #pragma unroll
        for (int mt = 0; mt < 4; mt++) {
            int m = m0 + wm*32 + mt*8 + colb;
            size_t o0 = ((size_t)(b*C1_ + cb))*N1_ + m;
            size_t o1 = ((size_t)(b*C1_ + cb + 8))*N1_ + m;
            float2 x0 = *(const float2*)(x1 + o0);
            float2 x1v = *(const float2*)(x1 + o1);
            *(float2*)(out + o0) = make_float2(fmaf(x0.x, cw0, acc[ct][mt][0]),
                                               fmaf(x0.y, cw0, acc[ct][mt][1]));
            *(float2*)(out + o1) = make_float2(fmaf(x1v.x, cw1, acc[ct][mt][2]),
                                               fmaf(x1v.y, cw1, acc[ct][mt][3]));
        }
    }
}

// ---------------------------------------------------------------------------
extern "C" void kernel_launch(void* const* d_in, const int* in_sizes, int n_in,
                              void* d_out, int out_size)
{
    (void)in_sizes; (void)n_in; (void)out_size;
    const float* x1  = (const float*)d_in[0];
    const float* x2  = (const float*)d_in[1];
    const float* wq  = (const float*)d_in[2];
    const float* wk  = (const float*)d_in[3];
    const float* wv  = (const float*)d_in[4];
    const float* wc  = (const float*)d_in[5];
    const float* wch = (const float*)d_in[6];
    const float* wt1 = (const float*)d_in[7];
    const float* bt1 = (const float*)d_in[8];
    const float* lng = (const float*)d_in[9];
    const float* lnb = (const float*)d_in[10];
    const float* wt2 = (const float*)d_in[11];
    const float* bt2 = (const float*)d_in[12];
    float* out = (float*)d_out;

    cudaFuncSetAttribute(attn_y_k, cudaFuncAttributeMaxDynamicSharedMemorySize,
                         SF_SMEM);

    // 1) prep: im2col x2/x1, weight splits, cf logits (all concurrent)
    prep_k<<<8160, 256>>>(x1, x2, wq, wk, wv, wc);
    // 2) gemms: conv_v + conv_q + conv_k + cf softmax (all concurrent)
    gemms_k<<<296, 256>>>();
    // 3) fused S-GEMM+softmax and y-pooling (concurrent)
    attn_y_k<<<dim3(384, B_), 512, SF_SMEM>>>(x1);
    // 4) channel tail (now coalesced warp-GEMVs)
    chtail_k<<<B_, 256>>>(wch, wt1, bt1, lng, lnb, wt2, bt2);
    // 5) O-GEMM + fused epilogue
    o_mma_k<<<dim3(N1_/128, C1_/128, B_), 256>>>(x1, out);
}